// round 15
// baseline (speedup 1.0000x reference)
#include <cuda_runtime.h>
#include <math.h>
#include <stdint.h>

#define Bc   2
#define Sc   2048
#define HIDc 1024
#define Hc   16
#define Dc   64

// ---------------------------------------------------------------------------
// Device scratch
// ---------------------------------------------------------------------------
__device__ uint32_t g_inqh[4096 * 512], g_inql[4096 * 512];
__device__ uint32_t g_inkh[4096 * 512], g_inkl[4096 * 512];
__device__ uint32_t g_invh[4096 * 512], g_invl[4096 * 512];
// Weights packed TRANSPOSED (n-major): [n][kp]
__device__ uint32_t g_wqh[1024 * 512], g_wql[1024 * 512];
__device__ uint32_t g_wkh[64 * 512],   g_wkl[64 * 512];
__device__ uint32_t g_wvh[64 * 512],   g_wvl[64 * 512];
__device__ uint32_t g_dwh[1024 * 512], g_dwl[1024 * 512];
__device__ uint32_t g_qh[4096 * 512],  g_ql[4096 * 512];
__device__ uint4 g_khl[512 * 4 * 32];
__device__ uint4 g_vhl[16 * 128 * 32];
__device__ uint32_t g_ctxh[4096 * 512], g_ctxl[4096 * 512];

// ---------------------------------------------------------------------------
// helpers
// ---------------------------------------------------------------------------
__device__ __forceinline__ uint32_t packbf(float x0, float x1) {
    uint32_t r;
    asm("cvt.rn.bf16x2.f32 %0, %1, %2;" : "=r"(r) : "f"(x1), "f"(x0));
    return r;
}
__device__ __forceinline__ float blo(uint32_t u) { return __uint_as_float(u << 16); }
__device__ __forceinline__ float bhi(uint32_t u) { return __uint_as_float(u & 0xffff0000u); }

__device__ __forceinline__ void split2(float x0, float x1, uint32_t& h, uint32_t& l) {
    h = packbf(x0, x1);
    l = packbf(x0 - blo(h), x1 - bhi(h));
}

__device__ __forceinline__ uint32_t packf16(float x0, float x1) {
    uint32_t r;
    asm("cvt.rn.f16x2.f32 %0, %1, %2;" : "=r"(r) : "f"(x1), "f"(x0));
    return r;
}
__device__ __forceinline__ float2 unpackf16(uint32_t u) {
    float lo, hi;
    asm("{.reg .f16 l, h;\n\t"
        " mov.b32 {l, h}, %2;\n\t"
        " cvt.f32.f16 %0, l;\n\t"
        " cvt.f32.f16 %1, h;}"
        : "=f"(lo), "=f"(hi) : "r"(u));
    return make_float2(lo, hi);
}
__device__ __forceinline__ void splitf16(float x0, float x1, uint32_t& h, uint32_t& l) {
    h = packf16(x0, x1);
    float2 r = unpackf16(h);
    l = packf16(x0 - r.x, x1 - r.y);
}

__device__ __forceinline__ void mma16(float* d, const uint32_t* a, uint32_t b0, uint32_t b1) {
    asm volatile(
        "mma.sync.aligned.m16n8k16.row.col.f32.bf16.bf16.f32 "
        "{%0,%1,%2,%3}, {%4,%5,%6,%7}, {%8,%9}, {%0,%1,%2,%3};"
        : "+f"(d[0]), "+f"(d[1]), "+f"(d[2]), "+f"(d[3])
        : "r"(a[0]), "r"(a[1]), "r"(a[2]), "r"(a[3]), "r"(b0), "r"(b1));
}
__device__ __forceinline__ void mma16f(float* d, const uint32_t* a, uint32_t b0, uint32_t b1) {
    asm volatile(
        "mma.sync.aligned.m16n8k16.row.col.f32.f16.f16.f32 "
        "{%0,%1,%2,%3}, {%4,%5,%6,%7}, {%8,%9}, {%0,%1,%2,%3};"
        : "+f"(d[0]), "+f"(d[1]), "+f"(d[2]), "+f"(d[3])
        : "r"(a[0]), "r"(a[1]), "r"(a[2]), "r"(a[3]), "r"(b0), "r"(b1));
}

#define LDSM_X4(r0, r1, r2, r3, addr) \
    asm volatile("ldmatrix.sync.aligned.m8n8.x4.shared.b16 {%0,%1,%2,%3}, [%4];" \
                 : "=r"(r0), "=r"(r1), "=r"(r2), "=r"(r3) : "r"(addr))
#define LDSM_X2(r0, r1, addr) \
    asm volatile("ldmatrix.sync.aligned.m8n8.x2.shared.b16 {%0,%1}, [%2];" \
                 : "=r"(r0), "=r"(r1) : "r"(addr))

__device__ __forceinline__ float ex2f(float x) {
    float r;
    asm("ex2.approx.f32 %0, %1;" : "=f"(r) : "f"(x));
    return r;
}

__device__ __forceinline__ int perm8(int kp) {
    int w = kp & 7;
    return (kp & ~7) | ((w < 4) ? (2 * w) : (2 * (w - 4) + 1));
}

// ---------------------------------------------------------------------------
// Mega-pack (weights stored transposed n-major)
// ---------------------------------------------------------------------------
#define NIN  (4096 * 512)
#define NWQ  (512 * 1024)
#define NWK  (512 * 64)

__global__ void pack_all(
    const float* __restrict__ q,  const float* __restrict__ k,  const float* __restrict__ v,
    const float* __restrict__ wq, const float* __restrict__ wk, const float* __restrict__ wv,
    const float* __restrict__ dw,
    uint32_t* __restrict__ qh, uint32_t* __restrict__ ql,
    uint32_t* __restrict__ kh, uint32_t* __restrict__ kl,
    uint32_t* __restrict__ vh, uint32_t* __restrict__ vl,
    uint32_t* __restrict__ wqh, uint32_t* __restrict__ wql,
    uint32_t* __restrict__ wkh, uint32_t* __restrict__ wkl,
    uint32_t* __restrict__ wvh, uint32_t* __restrict__ wvl,
    uint32_t* __restrict__ dwh, uint32_t* __restrict__ dwl)
{
    int i = blockIdx.x * blockDim.x + threadIdx.x;
    uint32_t h, l;
    if (i < NIN) {
        float2 t = *(const float2*)&q[2 * i];
        split2(t.x, t.y, h, l); qh[i] = h; ql[i] = l; return;
    }
    i -= NIN;
    if (i < NIN) {
        float2 t = *(const float2*)&k[2 * i];
        split2(t.x, t.y, h, l); kh[i] = h; kl[i] = l; return;
    }
    i -= NIN;
    if (i < NIN) {
        float2 t = *(const float2*)&v[2 * i];
        split2(t.x, t.y, h, l); vh[i] = h; vl[i] = l; return;
    }
    i -= NIN;
    if (i < NWQ) {
        int rp = i >> 10, c = i & 1023;
        split2(wq[(size_t)(2 * rp) * 1024 + c], wq[(size_t)(2 * rp + 1) * 1024 + c], h, l);
        wqh[(size_t)c * 512 + rp] = h; wql[(size_t)c * 512 + rp] = l; return;
    }
    i -= NWQ;
    if (i < NWQ) {
        int rp = i >> 10, c = i & 1023;
        split2(dw[(size_t)(2 * rp) * 1024 + c], dw[(size_t)(2 * rp + 1) * 1024 + c], h, l);
        dwh[(size_t)c * 512 + rp] = h; dwl[(size_t)c * 512 + rp] = l; return;
    }
    i -= NWQ;
    if (i < NWK) {
        int rp = i >> 6, c = i & 63;
        split2(wk[(size_t)(2 * rp) * 64 + c], wk[(size_t)(2 * rp + 1) * 64 + c], h, l);
        wkh[(size_t)c * 512 + rp] = h; wkl[(size_t)c * 512 + rp] = l; return;
    }
    i -= NWK;
    if (i < NWK) {
        int rp = i >> 6, c = i & 63;
        split2(wv[(size_t)(2 * rp) * 64 + c], wv[(size_t)(2 * rp + 1) * 64 + c], h, l);
        wvh[(size_t)c * 512 + rp] = h; wvl[(size_t)c * 512 + rp] = l; return;
    }
}

// ---------------------------------------------------------------------------
// Dense GEMM (f32 out + bias). ldmatrix fragment loads; B n-major transposed.
// ---------------------------------------------------------------------------
__global__ __launch_bounds__(256) void gemm_pk(
    const uint32_t* __restrict__ Ah, const uint32_t* __restrict__ Al,
    const uint32_t* __restrict__ BhT, const uint32_t* __restrict__ BlT,
    const float* __restrict__ bias, float* __restrict__ Cf,
    int M, int N, int K)
{
    __shared__ uint32_t ah[64][20], al[64][20];
    __shared__ uint32_t bh[64][20], bl[64][20];

    const int tid  = threadIdx.x;
    const int warp = tid >> 5;
    const int lane = tid & 31;
    const int gr   = lane >> 2;
    const int tig  = lane & 3;
    const int wm   = (warp & 3) * 16;
    const int wn   = (warp >> 2) * 32;

    const int m0 = blockIdx.y * 64;
    const int n0 = blockIdx.x * 64;
    const int Kp = K >> 1;

    const int arow = tid >> 2;
    const int akp  = (tid & 3) * 4;

    const uint32_t ahb = (uint32_t)__cvta_generic_to_shared(ah);
    const uint32_t alb = (uint32_t)__cvta_generic_to_shared(al);
    const uint32_t bhb = (uint32_t)__cvta_generic_to_shared(bh);
    const uint32_t blb = (uint32_t)__cvta_generic_to_shared(bl);
    const uint32_t aoff = (uint32_t)(((wm + (lane & 15)) * 20 + (lane >> 4) * 4) * 4);
    const uint32_t boff = (uint32_t)(((wn + (lane & 7)) * 20 + ((lane >> 3) & 1) * 4) * 4);

    float HH[4][4], HL[4][4], LH[4][4];
    #pragma unroll
    for (int n8 = 0; n8 < 4; n8++)
        #pragma unroll
        for (int i = 0; i < 4; i++) { HH[n8][i] = 0.f; HL[n8][i] = 0.f; LH[n8][i] = 0.f; }

    uint4 avh = *(const uint4*)&Ah[(size_t)(m0 + arow) * Kp + akp];
    uint4 avl = *(const uint4*)&Al[(size_t)(m0 + arow) * Kp + akp];
    uint4 bvh = *(const uint4*)&BhT[(size_t)(n0 + arow) * Kp + akp];
    uint4 bvl = *(const uint4*)&BlT[(size_t)(n0 + arow) * Kp + akp];

    for (int kp0 = 0; kp0 < Kp; kp0 += 16) {
        __syncthreads();
        *(uint4*)&ah[arow][akp] = avh;
        *(uint4*)&al[arow][akp] = avl;
        *(uint4*)&bh[arow][akp] = bvh;
        *(uint4*)&bl[arow][akp] = bvl;
        if (kp0 + 16 < Kp) {
            avh = *(const uint4*)&Ah[(size_t)(m0 + arow) * Kp + kp0 + 16 + akp];
            avl = *(const uint4*)&Al[(size_t)(m0 + arow) * Kp + kp0 + 16 + akp];
            bvh = *(const uint4*)&BhT[(size_t)(n0 + arow) * Kp + kp0 + 16 + akp];
            bvl = *(const uint4*)&BlT[(size_t)(n0 + arow) * Kp + kp0 + 16 + akp];
        }
        __syncthreads();

        #pragma unroll
        for (int kk = 0; kk < 2; kk++) {
            const uint32_t kb4 = (uint32_t)(kk * 8 * 4);
            uint32_t Ah4[4], Al4[4];
            LDSM_X4(Ah4[0], Ah4[1], Ah4[2], Ah4[3], ahb + aoff + kb4);
            LDSM_X4(Al4[0], Al4[1], Al4[2], Al4[3], alb + aoff + kb4);
            #pragma unroll
            for (int n8 = 0; n8 < 4; n8++) {
                const uint32_t noff = (uint32_t)(n8 * 8 * 20 * 4);
                uint32_t b0h, b1h, b0l, b1l;
                LDSM_X2(b0h, b1h, bhb + boff + noff + kb4);
                LDSM_X2(b0l, b1l, blb + boff + noff + kb4);
                mma16(HH[n8], Ah4, b0h, b1h);
                mma16(HL[n8], Ah4, b0l, b1l);
                mma16(LH[n8], Al4, b0h, b1h);
            }
        }
    }

    #pragma unroll
    for (int n8 = 0; n8 < 4; n8++) {
        const int col = n0 + wn + n8 * 8 + 2 * tig;
        const float2 bb = *(const float2*)&bias[col];
        float c0 = (HH[n8][0] + HL[n8][0]) + LH[n8][0] + bb.x;
        float c1 = (HH[n8][1] + HL[n8][1]) + LH[n8][1] + bb.y;
        float c2 = (HH[n8][2] + HL[n8][2]) + LH[n8][2] + bb.x;
        float c3 = (HH[n8][3] + HL[n8][3]) + LH[n8][3] + bb.y;
        *(float2*)&Cf[(size_t)(m0 + wm + gr) * N + col]     = make_float2(c0, c1);
        *(float2*)&Cf[(size_t)(m0 + wm + gr + 8) * N + col] = make_float2(c2, c3);
    }
}

// ---------------------------------------------------------------------------
// Merged Q/K/V projection with ldmatrix fragments. grid (18, 64).
// ---------------------------------------------------------------------------
__global__ __launch_bounds__(256) void gemm_qkv(
    const uint32_t* __restrict__ AhQ, const uint32_t* __restrict__ AlQ,
    const uint32_t* __restrict__ AhK, const uint32_t* __restrict__ AlK,
    const uint32_t* __restrict__ AhV, const uint32_t* __restrict__ AlV,
    const uint32_t* __restrict__ BhQ, const uint32_t* __restrict__ BlQ,
    const float* __restrict__ biasQ,
    const uint32_t* __restrict__ BhK, const uint32_t* __restrict__ BlK,
    const float* __restrict__ biasK,
    const uint32_t* __restrict__ BhV, const uint32_t* __restrict__ BlV,
    const float* __restrict__ biasV,
    uint32_t* __restrict__ Qh, uint32_t* __restrict__ Ql, float qscale,
    uint4* __restrict__ Khl, uint4* __restrict__ Vhl)
{
    __shared__ uint32_t ah[64][20], al[64][20];
    __shared__ uint32_t bh[64][20], bl[64][20];

    const int sel = blockIdx.x;               // 0..15 Q, 16 K, 17 V
    const int isQ = (sel < 16);
    const uint32_t* Ah = isQ ? AhQ : (sel == 16 ? AhK : AhV);
    const uint32_t* Al = isQ ? AlQ : (sel == 16 ? AlK : AlV);
    const uint32_t* BhT = isQ ? BhQ : (sel == 16 ? BhK : BhV);
    const uint32_t* BlT = isQ ? BlQ : (sel == 16 ? BlK : BlV);
    const float*  bias = isQ ? biasQ : (sel == 16 ? biasK : biasV);
    const int n0 = isQ ? sel * 64 : 0;

    const int tid  = threadIdx.x;
    const int warp = tid >> 5;
    const int lane = tid & 31;
    const int gr   = lane >> 2;
    const int tig  = lane & 3;
    const int wm   = (warp & 3) * 16;
    const int wsel = warp >> 2;
    const int wn   = wsel * 32;

    const int m0 = blockIdx.y * 64;
    const int Kp = 512;

    const int arow = tid >> 2;
    const int akp  = (tid & 3) * 4;

    const uint32_t ahb = (uint32_t)__cvta_generic_to_shared(ah);
    const uint32_t alb = (uint32_t)__cvta_generic_to_shared(al);
    const uint32_t bhb = (uint32_t)__cvta_generic_to_shared(bh);
    const uint32_t blb = (uint32_t)__cvta_generic_to_shared(bl);
    const uint32_t aoff = (uint32_t)(((wm + (lane & 15)) * 20 + (lane >> 4) * 4) * 4);
    const uint32_t boff = (uint32_t)(((wn + (lane & 7)) * 20 + ((lane >> 3) & 1) * 4) * 4);

    float HH[4][4], HL[4][4], LH[4][4];
    #pragma unroll
    for (int n8 = 0; n8 < 4; n8++)
        #pragma unroll
        for (int i = 0; i < 4; i++) { HH[n8][i] = 0.f; HL[n8][i] = 0.f; LH[n8][i] = 0.f; }

    uint4 avh = *(const uint4*)&Ah[(size_t)(m0 + arow) * Kp + akp];
    uint4 avl = *(const uint4*)&Al[(size_t)(m0 + arow) * Kp + akp];
    uint4 bvh = *(const uint4*)&BhT[(size_t)(n0 + arow) * Kp + akp];
    uint4 bvl = *(const uint4*)&BlT[(size_t)(n0 + arow) * Kp + akp];

    for (int kp0 = 0; kp0 < Kp; kp0 += 16) {
        __syncthreads();
        *(uint4*)&ah[arow][akp] = avh;
        *(uint4*)&al[arow][akp] = avl;
        *(uint4*)&bh[arow][akp] = bvh;
        *(uint4*)&bl[arow][akp] = bvl;
        if (kp0 + 16 < Kp) {
            avh = *(const uint4*)&Ah[(size_t)(m0 + arow) * Kp + kp0 + 16 + akp];
            avl = *(const uint4*)&Al[(size_t)(m0 + arow) * Kp + kp0 + 16 + akp];
            bvh = *(const uint4*)&BhT[(size_t)(n0 + arow) * Kp + kp0 + 16 + akp];
            bvl = *(const uint4*)&BlT[(size_t)(n0 + arow) * Kp + kp0 + 16 + akp];
        }
        __syncthreads();

        #pragma unroll
        for (int kk = 0; kk < 2; kk++) {
            const uint32_t kb4 = (uint32_t)(kk * 8 * 4);
            uint32_t Ah4[4], Al4[4];
            LDSM_X4(Ah4[0], Ah4[1], Ah4[2], Ah4[3], ahb + aoff + kb4);
            LDSM_X4(Al4[0], Al4[1], Al4[2], Al4[3], alb + aoff + kb4);
            #pragma unroll
            for (int n8 = 0; n8 < 4; n8++) {
                const uint32_t noff = (uint32_t)(n8 * 8 * 20 * 4);
                uint32_t b0h, b1h, b0l, b1l;
                LDSM_X2(b0h, b1h, bhb + boff + noff + kb4);
                LDSM_X2(b0l, b1l, blb + boff + noff + kb4);
                mma16(HH[n8], Ah4, b0h, b1h);
                mma16(HL[n8], Ah4, b0l, b1l);
                mma16(LH[n8], Al4, b0h, b1h);
            }
        }
    }

    float R0[4], R1[4], R2[4], R3[4];
    #pragma unroll
    for (int n8 = 0; n8 < 4; n8++) {
        const int col = n0 + wn + n8 * 8 + 2 * tig;
        const float2 bb = *(const float2*)&bias[col];
        R0[n8] = (HH[n8][0] + HL[n8][0]) + LH[n8][0] + bb.x;
        R1[n8] = (HH[n8][1] + HL[n8][1]) + LH[n8][1] + bb.y;
        R2[n8] = (HH[n8][2] + HL[n8][2]) + LH[n8][2] + bb.x;
        R3[n8] = (HH[n8][3] + HL[n8][3]) + LH[n8][3] + bb.y;
    }

    if (isQ) {
        #pragma unroll
        for (int n8 = 0; n8 < 4; n8++) {
            const int col = n0 + wn + n8 * 8 + 2 * tig;
            float c0 = R0[n8] * qscale, c1 = R1[n8] * qscale;
            float c2 = R2[n8] * qscale, c3 = R3[n8] * qscale;
            const int pk = perm8(col >> 1);
            uint32_t H, L;
            split2(c0, c1, H, L);
            Qh[(size_t)(m0 + wm + gr) * 512 + pk] = H;
            Ql[(size_t)(m0 + wm + gr) * 512 + pk] = L;
            split2(c2, c3, H, L);
            Qh[(size_t)(m0 + wm + gr + 8) * 512 + pk] = H;
            Ql[(size_t)(m0 + wm + gr + 8) * 512 + pk] = L;
        }
    } else if (sel == 16) {
        uint32_t H[4], L[4], H8[4], L8[4];
        #pragma unroll
        for (int n8 = 0; n8 < 4; n8++) {
            split2(R0[n8], R1[n8], H[n8],  L[n8]);
            split2(R2[n8], R3[n8], H8[n8], L8[n8]);
        }
        const int rg0 = (m0 + wm + gr) >> 3;
        const int rg8 = rg0 + 1;
        const int u   = gr * 4 + tig;
        const int kk0 = 2 * wsel;
        Khl[(size_t)(rg0 * 4 + kk0) * 32 + u]     = make_uint4(H[0],  H[1],  L[0],  L[1]);
        Khl[(size_t)(rg0 * 4 + kk0 + 1) * 32 + u] = make_uint4(H[2],  H[3],  L[2],  L[3]);
        Khl[(size_t)(rg8 * 4 + kk0) * 32 + u]     = make_uint4(H8[0], H8[1], L8[0], L8[1]);
        Khl[(size_t)(rg8 * 4 + kk0 + 1) * 32 + u] = make_uint4(H8[2], H8[3], L8[2], L8[3]);
    } else {
        #pragma unroll
        for (int n8 = 0; n8 < 4; n8++) {
            const int col = wn + n8 * 8 + 2 * tig;
            float p0 = __shfl_down_sync(0xffffffffu, R0[n8], 4);
            float p1 = __shfl_down_sync(0xffffffffu, R1[n8], 4);
            float p2 = __shfl_down_sync(0xffffffffu, R2[n8], 4);
            float p3 = __shfl_down_sync(0xffffffffu, R3[n8], 4);
            if ((gr & 1) == 0) {
                const int ra  = m0 + wm + gr;
                const int b2  = ra >> 11;
                const int kpa = (ra & 2047) >> 1;
                const int kpc = kpa >> 3;
                const int tl  = gr >> 1;
                uint32_t Ha, La, Hb, Lb;
                splitf16(R0[n8], p0, Ha, La);
                splitf16(R2[n8], p2, Hb, Lb);
                Vhl[((size_t)(b2 * 8 + (col >> 3)) * 128 + kpc) * 32 + (col & 7) * 4 + tl]
                    = make_uint4(Ha, Hb, La, Lb);
                splitf16(R1[n8], p1, Ha, La);
                splitf16(R3[n8], p3, Hb, Lb);
                Vhl[((size_t)(b2 * 8 + (col >> 3)) * 128 + kpc) * 32 + ((col + 1) & 7) * 4 + tl]
                    = make_uint4(Ha, Hb, La, Lb);
            }
        }
    }
}

// ---------------------------------------------------------------------------
// Fused attention (unchanged from R14). One CTA = (b, h, 32 q-rows).
// ---------------------------------------------------------------------------
#define QR   32
#define PP   1028
#define WSTR 2176

__global__ __launch_bounds__(512, 1) void attn_kernel(
    const uint32_t* __restrict__ qh,  const uint32_t* __restrict__ ql,
    const uint4* __restrict__ khl, const uint4* __restrict__ vhl,
    float* __restrict__ attn, uint32_t* __restrict__ ctxh, uint32_t* __restrict__ ctxl,
    int write_attn)
{
    extern __shared__ uint32_t su[];
    uint32_t* ph = su;
    uint4*    qf = (uint4*)(su + QR * PP);
    float*   red = (float*)((char*)su + 139264);
    float* inv_s = red + 512;

    const int tid  = threadIdx.x;
    const int warp = tid >> 5;
    const int lane = tid & 31;
    const int gr   = lane >> 2;
    const int tig  = lane & 3;

    const int qt = blockIdx.x & 63;
    const int h  = (blockIdx.x >> 6) & (Hc - 1);
    const int b  = blockIdx.x >> 10;
    const int q0 = qt * QR;

    const uint32_t pha = (uint32_t)__cvta_generic_to_shared(ph);

    uint32_t QAh[4][4], QAl[4][4];
    {
        const uint32_t* q0p = &qh[(size_t)(b * Sc + q0 + gr) * 512 + h * 32 + 2 * tig];
        const uint32_t* q8p = q0p + 8 * 512;
        const uint32_t* q0l = &ql[(size_t)(b * Sc + q0 + gr) * 512 + h * 32 + 2 * tig];
        const uint32_t* q8l = q0l + 8 * 512;
        #pragma unroll
        for (int kk = 0; kk < 4; kk++) {
            uint2 a02 = *(const uint2*)&q0p[kk * 8];
            uint2 a13 = *(const uint2*)&q8p[kk * 8];
            QAh[kk][0] = a02.x; QAh[kk][2] = a02.y;
            QAh[kk][1] = a13.x; QAh[kk][3] = a13.y;
            a02 = *(const uint2*)&q0l[kk * 8];
            a13 = *(const uint2*)&q8l[kk * 8];
            QAl[kk][0] = a02.x; QAl[kk][2] = a02.y;
            QAl[kk][1] = a13.x; QAl[kk][3] = a13.y;
        }
    }

    if (warp < 4) {
        const int kk = warp;
        const uint32_t* q0p = &qh[(size_t)(b * Sc + q0 + 16 + gr) * 512 + h * 32 + 2 * tig];
        const uint32_t* q8p = q0p + 8 * 512;
        const uint32_t* q0l = &ql[(size_t)(b * Sc + q0 + 16 + gr) * 512 + h * 32 + 2 * tig];
        const uint32_t* q8l = q0l + 8 * 512;
        uint2 a02 = *(const uint2*)&q0p[kk * 8];
        uint2 a13 = *(const uint2*)&q8p[kk * 8];
        qf[(kk * 2 + 0) * 32 + lane] = make_uint4(a02.x, a13.x, a02.y, a13.y);
        a02 = *(const uint2*)&q0l[kk * 8];
        a13 = *(const uint2*)&q8l[kk * 8];
        qf[(kk * 2 + 1) * 32 + lane] = make_uint4(a02.x, a13.x, a02.y, a13.y);
    }
    __syncthreads();

    float s0 = 0.0f, s1 = 0.0f, s2 = 0.0f, s3 = 0.0f;
    {
        const uint4* kf = khl + ((size_t)(b * 256 + warp) * 4) * 32 + lane;

        #pragma unroll 2
        for (int t = 0; t < 16; t++) {
            const uint4* kt = kf + (size_t)t * 2048;
            float hh0[4] = {0,0,0,0}, hl0[4] = {0,0,0,0}, lh0[4] = {0,0,0,0};
            float hh1[4] = {0,0,0,0}, hl1[4] = {0,0,0,0}, lh1[4] = {0,0,0,0};
            #pragma unroll
            for (int kk = 0; kk < 4; kk++) {
                uint4 kv4 = kt[kk * 32];
                mma16(hh0, QAh[kk], kv4.x, kv4.y);
                mma16(hl0, QAh[kk], kv4.z, kv4.w);
                mma16(lh0, QAl[kk], kv4.x, kv4.y);
                uint4 qh4 = qf[(kk * 2 + 0) * 32 + lane];
                uint4 ql4 = qf[(kk * 2 + 1) * 32 + lane];
                uint32_t Qh1[4] = { qh4.x, qh4.y, qh4.z, qh4.w };
                uint32_t Ql1[4] = { ql4.x, ql4.y, ql4.z, ql4.w };
                mma16(hh1, Qh1, kv4.x, kv4.y);
                mma16(hl1, Qh1, kv4.z, kv4.w);
                mma16(lh1, Ql1, kv4.x, kv4.y);
            }
            float e0 = ex2f((hh0[0] + hl0[0]) + lh0[0]);
            float e1 = ex2f((hh0[1] + hl0[1]) + lh0[1]);
            float e2 = ex2f((hh0[2] + hl0[2]) + lh0[2]);
            float e3 = ex2f((hh0[3] + hl0[3]) + lh0[3]);
            float e4 = ex2f((hh1[0] + hl1[0]) + lh1[0]);
            float e5 = ex2f((hh1[1] + hl1[1]) + lh1[1]);
            float e6 = ex2f((hh1[2] + hl1[2]) + lh1[2]);
            float e7 = ex2f((hh1[3] + hl1[3]) + lh1[3]);
            s0 += e0 + e1;
            s1 += e2 + e3;
            s2 += e4 + e5;
            s3 += e6 + e7;
            const int pc = t * 64 + warp * 4 + tig;
            ph[gr * PP + pc]        = packf16(e0, e1);
            ph[(gr + 8) * PP + pc]  = packf16(e2, e3);
            ph[(gr + 16) * PP + pc] = packf16(e4, e5);
            ph[(gr + 24) * PP + pc] = packf16(e6, e7);
        }
    }

    s0 += __shfl_xor_sync(0xffffffffu, s0, 1);
    s0 += __shfl_xor_sync(0xffffffffu, s0, 2);
    s1 += __shfl_xor_sync(0xffffffffu, s1, 1);
    s1 += __shfl_xor_sync(0xffffffffu, s1, 2);
    s2 += __shfl_xor_sync(0xffffffffu, s2, 1);
    s2 += __shfl_xor_sync(0xffffffffu, s2, 2);
    s3 += __shfl_xor_sync(0xffffffffu, s3, 1);
    s3 += __shfl_xor_sync(0xffffffffu, s3, 2);
    if (tig == 0) {
        red[warp * 32 + gr]      = s0;
        red[warp * 32 + gr + 8]  = s1;
        red[warp * 32 + gr + 16] = s2;
        red[warp * 32 + gr + 24] = s3;
    }
    __syncthreads();

    {
        #pragma unroll
        for (int rr = 0; rr < 2; rr++) {
            const int r = warp * 2 + rr;
            float s = (lane < 16) ? red[lane * 32 + r] : 0.0f;
            #pragma unroll
            for (int o = 16; o; o >>= 1) s += __shfl_xor_sync(0xffffffffu, s, o);
            const float inv = 1.0f / s;
            if (lane == 0) inv_s[r] = inv;

            if (write_attn) {
                const uint32_t* rh = &ph[r * PP];
                size_t base = ((size_t)(b * Hc + h) * Sc + (q0 + r)) * (size_t)Sc;
                #pragma unroll
                for (int c = lane * 4; c < 1024; c += 128) {
                    uint4 h4 = *(const uint4*)&rh[c];
                    float2 p0 = unpackf16(h4.x);
                    float2 p1 = unpackf16(h4.y);
                    float2 p2 = unpackf16(h4.z);
                    float2 p3 = unpackf16(h4.w);
                    __stcs((float4*)&attn[base + 2 * c],
                           make_float4(p0.x * inv, p0.y * inv, p1.x * inv, p1.y * inv));
                    __stcs((float4*)&attn[base + 2 * c + 4],
                           make_float4(p2.x * inv, p2.y * inv, p3.x * inv, p3.y * inv));
                }
            }
        }
    }
    __syncthreads();

    {
        float acc0[8][4], acc1[8][4];
        #pragma unroll
        for (int nt = 0; nt < 8; nt++)
            #pragma unroll
            for (int i = 0; i < 4; i++) { acc0[nt][i] = 0.f; acc1[nt][i] = 0.f; }

        const uint32_t poff = (uint32_t)((((lane & 7) + ((lane >> 3) & 1) * 8) * PP
                                          + ((lane >> 4) & 1) * 4) * 4);
        const uint32_t t1off = (uint32_t)(16 * PP * 4);
        const uint4* vb = vhl + (size_t)(b * 8) * 128 * 32 + lane;

        #pragma unroll 2
        for (int cc = 0; cc < 8; cc++) {
            const int c = warp * 8 + cc;
            uint32_t Pa[4], Pb[4];
            LDSM_X4(Pa[0], Pa[1], Pa[2], Pa[3], pha + poff + (uint32_t)(c * 32));
            LDSM_X4(Pb[0], Pb[1], Pb[2], Pb[3], pha + poff + t1off + (uint32_t)(c * 32));
            #pragma unroll
            for (int nt = 0; nt < 8; nt++) {
                uint4 vv = vb[((size_t)nt * 128 + c) * 32];
                mma16f(acc0[nt], Pa, vv.x, vv.y);
                mma16f(acc0[nt], Pa, vv.z, vv.w);
                mma16f(acc1[nt], Pb, vv.x, vv.y);
                mma16f(acc1[nt], Pb, vv.z, vv.w);
            }
        }

        __syncthreads();

        float* wred = (float*)su + warp * WSTR;
        #pragma unroll
        for (int nt = 0; nt < 8; nt++) {
            const int nc = nt * 8 + 2 * tig;
            *(float2*)&wred[gr * 68 + nc]        = make_float2(acc0[nt][0], acc0[nt][1]);
            *(float2*)&wred[(gr + 8) * 68 + nc]  = make_float2(acc0[nt][2], acc0[nt][3]);
            *(float2*)&wred[(gr + 16) * 68 + nc] = make_float2(acc1[nt][0], acc1[nt][1]);
            *(float2*)&wred[(gr + 24) * 68 + nc] = make_float2(acc1[nt][2], acc1[nt][3]);
        }
        __syncthreads();

        const int e = tid * 4;
        const int q = e >> 6;
        const int n = e & 63;
        float4 s4 = make_float4(0.f, 0.f, 0.f, 0.f);
        const float* rb = (float*)su + q * 68 + n;
        #pragma unroll
        for (int w = 0; w < 16; w++) {
            float4 t4 = *(const float4*)&rb[w * WSTR];
            s4.x += t4.x; s4.y += t4.y; s4.z += t4.z; s4.w += t4.w;
        }
        const float inv = inv_s[q];
        s4.x *= inv; s4.y *= inv; s4.z *= inv; s4.w *= inv;
        uint32_t H, L;
        const size_t row = (size_t)(b * Sc + q0 + q) * 512 + h * 32 + (n >> 1);
        split2(s4.x, s4.y, H, L);
        ctxh[row] = H; ctxl[row] = L;
        split2(s4.z, s4.w, H, L);
        ctxh[row + 1] = H; ctxl[row + 1] = L;
    }
}

// ---------------------------------------------------------------------------
extern "C" void kernel_launch(void* const* d_in, const int* in_sizes, int n_in,
                              void* d_out, int out_size)
{
    const float* query   = (const float*)d_in[0];
    const float* key     = (const float*)d_in[1];
    const float* value   = (const float*)d_in[2];
    const float* wq_w    = (const float*)d_in[3];
    const float* wq_b    = (const float*)d_in[4];
    const float* wk_w    = (const float*)d_in[5];
    const float* wk_b    = (const float*)d_in[6];
    const float* wv_w    = (const float*)d_in[7];
    const float* wv_b    = (const float*)d_in[8];
    const float* dense_w = (const float*)d_in[9];
    const float* dense_b = (const float*)d_in[10];

    float* out = (float*)d_out;
    const long long OUT = (long long)Bc * Sc * HIDc;
    const long long ATT = (long long)Bc * Hc * Sc * Sc;
    const int write_attn = ((long long)out_size >= OUT + ATT) ? 1 : 0;
    float* attn = out + OUT;

    uint32_t *inqh, *inql, *inkh, *inkl, *invh, *invl;
    uint32_t *wqh, *wql, *wkh, *wkl, *wvh, *wvl, *dwh, *dwl;
    uint32_t *qh, *ql, *ctxh, *ctxl;
    uint4 *khl, *vhl;
    cudaGetSymbolAddress((void**)&inqh, g_inqh);
    cudaGetSymbolAddress((void**)&inql, g_inql);
    cudaGetSymbolAddress((void**)&inkh, g_inkh);
    cudaGetSymbolAddress((void**)&inkl, g_inkl);
    cudaGetSymbolAddress((void**)&invh, g_invh);
    cudaGetSymbolAddress((void**)&invl, g_invl);
    cudaGetSymbolAddress((void**)&wqh, g_wqh);
    cudaGetSymbolAddress((void**)&wql, g_wql);
    cudaGetSymbolAddress((void**)&wkh, g_wkh);
    cudaGetSymbolAddress((void**)&wkl, g_wkl);
    cudaGetSymbolAddress((void**)&wvh, g_wvh);
    cudaGetSymbolAddress((void**)&wvl, g_wvl);
    cudaGetSymbolAddress((void**)&dwh, g_dwh);
    cudaGetSymbolAddress((void**)&dwl, g_dwl);
    cudaGetSymbolAddress((void**)&qh, g_qh);
    cudaGetSymbolAddress((void**)&ql, g_ql);
    cudaGetSymbolAddress((void**)&khl, g_khl);
    cudaGetSymbolAddress((void**)&vhl, g_vhl);
    cudaGetSymbolAddress((void**)&ctxh, g_ctxh);
    cudaGetSymbolAddress((void**)&ctxl, g_ctxl);

    const int M = Bc * Sc;  // 4096

    // launch #0: all packing (weights transposed n-major)
    const int NPK = 3 * NIN + 2 * NWQ + 2 * NWK;
    pack_all<<<(NPK + 255) / 256, 256>>>(query, key, value, wq_w, wk_w, wv_w, dense_w,
                                         inqh, inql, inkh, inkl, invh, invl,
                                         wqh, wql, wkh, wkl, wvh, wvl, dwh, dwl);

    // launch #1: merged q/k/v projections (ldmatrix fragments)
    const float QSCALE = 0.125f * 1.4426950408889634f;
    gemm_qkv<<<dim3(18, 64), 256>>>(inqh, inql, inkh, inkl, invh, invl,
                                    wqh, wql, wq_b, wkh, wkl, wk_b, wvh, wvl, wv_b,
                                    qh, ql, QSCALE, khl, vhl);

    // launch #2: fused attention (unchanged)
    const int smem = 139264 + (512 + 32) * 4;  // 141,440 B
    cudaFuncSetAttribute(attn_kernel, cudaFuncAttributeMaxDynamicSharedMemorySize, smem);
    attn_kernel<<<Bc * Hc * (Sc / QR), 512, smem>>>(qh, ql, khl, vhl,
                                                    attn, ctxh, ctxl, write_attn);

    // launch #3: output projection (ldmatrix fragments)
    gemm_pk<<<dim3(16, 64), 256>>>(ctxh, ctxl, dwh, dwl, dense_b, out, M, HIDc, HIDc);
}

// round 16
// speedup vs baseline: 1.0525x; 1.0525x over previous
#include <cuda_runtime.h>
#include <math.h>
#include <stdint.h>

#define Bc   2
#define Sc   2048
#define HIDc 1024
#define Hc   16
#define Dc   64

// ---------------------------------------------------------------------------
// Device scratch
// ---------------------------------------------------------------------------
__device__ uint32_t g_inqh[4096 * 512], g_inql[4096 * 512];
__device__ uint32_t g_inkh[4096 * 512], g_inkl[4096 * 512];
__device__ uint32_t g_invh[4096 * 512], g_invl[4096 * 512];
__device__ uint32_t g_wqh[512 * 1024], g_wql[512 * 1024];
__device__ uint32_t g_wkh[512 * 64],   g_wkl[512 * 64];
__device__ uint32_t g_wvh[512 * 64],   g_wvl[512 * 64];
__device__ uint32_t g_dwh[512 * 1024], g_dwl[512 * 1024];
__device__ uint32_t g_qh[4096 * 512],  g_ql[4096 * 512];
__device__ uint4 g_khl[512 * 4 * 32];
__device__ uint4 g_vhl[16 * 128 * 32];
__device__ uint32_t g_ctxh[4096 * 512], g_ctxl[4096 * 512];

// ---------------------------------------------------------------------------
// helpers
// ---------------------------------------------------------------------------
__device__ __forceinline__ uint32_t packbf(float x0, float x1) {
    uint32_t r;
    asm("cvt.rn.bf16x2.f32 %0, %1, %2;" : "=r"(r) : "f"(x1), "f"(x0));
    return r;
}
__device__ __forceinline__ float blo(uint32_t u) { return __uint_as_float(u << 16); }
__device__ __forceinline__ float bhi(uint32_t u) { return __uint_as_float(u & 0xffff0000u); }

__device__ __forceinline__ void split2(float x0, float x1, uint32_t& h, uint32_t& l) {
    h = packbf(x0, x1);
    l = packbf(x0 - blo(h), x1 - bhi(h));
}

__device__ __forceinline__ uint32_t packf16(float x0, float x1) {
    uint32_t r;
    asm("cvt.rn.f16x2.f32 %0, %1, %2;" : "=r"(r) : "f"(x1), "f"(x0));
    return r;
}
__device__ __forceinline__ float2 unpackf16(uint32_t u) {
    float lo, hi;
    asm("{.reg .f16 l, h;\n\t"
        " mov.b32 {l, h}, %2;\n\t"
        " cvt.f32.f16 %0, l;\n\t"
        " cvt.f32.f16 %1, h;}"
        : "=f"(lo), "=f"(hi) : "r"(u));
    return make_float2(lo, hi);
}
__device__ __forceinline__ void splitf16(float x0, float x1, uint32_t& h, uint32_t& l) {
    h = packf16(x0, x1);
    float2 r = unpackf16(h);
    l = packf16(x0 - r.x, x1 - r.y);
}

__device__ __forceinline__ void mma16(float* d, const uint32_t* a, uint32_t b0, uint32_t b1) {
    asm volatile(
        "mma.sync.aligned.m16n8k16.row.col.f32.bf16.bf16.f32 "
        "{%0,%1,%2,%3}, {%4,%5,%6,%7}, {%8,%9}, {%0,%1,%2,%3};"
        : "+f"(d[0]), "+f"(d[1]), "+f"(d[2]), "+f"(d[3])
        : "r"(a[0]), "r"(a[1]), "r"(a[2]), "r"(a[3]), "r"(b0), "r"(b1));
}
__device__ __forceinline__ void mma16f(float* d, const uint32_t* a, uint32_t b0, uint32_t b1) {
    asm volatile(
        "mma.sync.aligned.m16n8k16.row.col.f32.f16.f16.f32 "
        "{%0,%1,%2,%3}, {%4,%5,%6,%7}, {%8,%9}, {%0,%1,%2,%3};"
        : "+f"(d[0]), "+f"(d[1]), "+f"(d[2]), "+f"(d[3])
        : "r"(a[0]), "r"(a[1]), "r"(a[2]), "r"(a[3]), "r"(b0), "r"(b1));
}

#define LDSM_X4(r0, r1, r2, r3, addr) \
    asm volatile("ldmatrix.sync.aligned.m8n8.x4.shared.b16 {%0,%1,%2,%3}, [%4];" \
                 : "=r"(r0), "=r"(r1), "=r"(r2), "=r"(r3) : "r"(addr))

__device__ __forceinline__ float ex2f(float x) {
    float r;
    asm("ex2.approx.f32 %0, %1;" : "=f"(r) : "f"(x));
    return r;
}

__device__ __forceinline__ int perm8(int kp) {
    int w = kp & 7;
    return (kp & ~7) | ((w < 4) ? (2 * w) : (2 * (w - 4) + 1));
}

// ---------------------------------------------------------------------------
// Mega-pack (k-major weights, as in R14)
// ---------------------------------------------------------------------------
#define NIN  (4096 * 512)
#define NWQ  (512 * 1024)
#define NWK  (512 * 64)

__global__ void pack_all(
    const float* __restrict__ q,  const float* __restrict__ k,  const float* __restrict__ v,
    const float* __restrict__ wq, const float* __restrict__ wk, const float* __restrict__ wv,
    const float* __restrict__ dw,
    uint32_t* __restrict__ qh, uint32_t* __restrict__ ql,
    uint32_t* __restrict__ kh, uint32_t* __restrict__ kl,
    uint32_t* __restrict__ vh, uint32_t* __restrict__ vl,
    uint32_t* __restrict__ wqh, uint32_t* __restrict__ wql,
    uint32_t* __restrict__ wkh, uint32_t* __restrict__ wkl,
    uint32_t* __restrict__ wvh, uint32_t* __restrict__ wvl,
    uint32_t* __restrict__ dwh, uint32_t* __restrict__ dwl)
{
    int i = blockIdx.x * blockDim.x + threadIdx.x;
    uint32_t h, l;
    if (i < NIN) {
        float2 t = *(const float2*)&q[2 * i];
        split2(t.x, t.y, h, l); qh[i] = h; ql[i] = l; return;
    }
    i -= NIN;
    if (i < NIN) {
        float2 t = *(const float2*)&k[2 * i];
        split2(t.x, t.y, h, l); kh[i] = h; kl[i] = l; return;
    }
    i -= NIN;
    if (i < NIN) {
        float2 t = *(const float2*)&v[2 * i];
        split2(t.x, t.y, h, l); vh[i] = h; vl[i] = l; return;
    }
    i -= NIN;
    if (i < NWQ) {
        int rp = i >> 10, c = i & 1023;
        split2(wq[(size_t)(2 * rp) * 1024 + c], wq[(size_t)(2 * rp + 1) * 1024 + c], h, l);
        wqh[i] = h; wql[i] = l; return;
    }
    i -= NWQ;
    if (i < NWQ) {
        int rp = i >> 10, c = i & 1023;
        split2(dw[(size_t)(2 * rp) * 1024 + c], dw[(size_t)(2 * rp + 1) * 1024 + c], h, l);
        dwh[i] = h; dwl[i] = l; return;
    }
    i -= NWQ;
    if (i < NWK) {
        int rp = i >> 6, c = i & 63;
        split2(wk[(size_t)(2 * rp) * 64 + c], wk[(size_t)(2 * rp + 1) * 64 + c], h, l);
        wkh[i] = h; wkl[i] = l; return;
    }
    i -= NWK;
    if (i < NWK) {
        int rp = i >> 6, c = i & 63;
        split2(wv[(size_t)(2 * rp) * 64 + c], wv[(size_t)(2 * rp + 1) * 64 + c], h, l);
        wvh[i] = h; wvl[i] = l; return;
    }
}

// ---------------------------------------------------------------------------
// Dense GEMM. 128x64 CTA tile, m32xn32 per warp (LDS:MMA = 1.33).
// Correction terms (Ah*Bl + Al*Bh) merged into one accumulator.
// ---------------------------------------------------------------------------
__global__ __launch_bounds__(256) void gemm_pk(
    const uint32_t* __restrict__ Ah, const uint32_t* __restrict__ Al,
    const uint32_t* __restrict__ Bh, const uint32_t* __restrict__ Bl,
    const float* __restrict__ bias, float* __restrict__ Cf,
    int M, int N, int K)
{
    __shared__ uint32_t ah[128][20], al[128][20];
    __shared__ uint32_t bh[16][72],  bl[16][72];

    const int tid  = threadIdx.x;
    const int warp = tid >> 5;
    const int lane = tid & 31;
    const int gr   = lane >> 2;
    const int tig  = lane & 3;
    const int wm   = (warp & 3) * 32;
    const int wn   = (warp >> 2) * 32;

    const int m0 = blockIdx.y * 128;
    const int n0 = blockIdx.x * 64;
    const int Kp = K >> 1;

    const int arow = tid >> 1;          // 0..127
    const int akp  = (tid & 1) * 8;     // 0 or 8
    const int bkp  = tid >> 4;          // 0..15
    const int bn   = (tid & 15) * 4;

    float HH[2][4][4], CC[2][4][4];
    #pragma unroll
    for (int mt = 0; mt < 2; mt++)
        #pragma unroll
        for (int n8 = 0; n8 < 4; n8++)
            #pragma unroll
            for (int i = 0; i < 4; i++) { HH[mt][n8][i] = 0.f; CC[mt][n8][i] = 0.f; }

    uint4 avh0 = *(const uint4*)&Ah[(size_t)(m0 + arow) * Kp + akp];
    uint4 avh1 = *(const uint4*)&Ah[(size_t)(m0 + arow) * Kp + akp + 4];
    uint4 avl0 = *(const uint4*)&Al[(size_t)(m0 + arow) * Kp + akp];
    uint4 avl1 = *(const uint4*)&Al[(size_t)(m0 + arow) * Kp + akp + 4];
    uint4 bvh  = *(const uint4*)&Bh[(size_t)bkp * N + n0 + bn];
    uint4 bvl  = *(const uint4*)&Bl[(size_t)bkp * N + n0 + bn];

    for (int kp0 = 0; kp0 < Kp; kp0 += 16) {
        __syncthreads();
        *(uint4*)&ah[arow][akp]     = avh0;
        *(uint4*)&ah[arow][akp + 4] = avh1;
        *(uint4*)&al[arow][akp]     = avl0;
        *(uint4*)&al[arow][akp + 4] = avl1;
        *(uint4*)&bh[bkp][bn] = bvh;
        *(uint4*)&bl[bkp][bn] = bvl;
        if (kp0 + 16 < Kp) {
            avh0 = *(const uint4*)&Ah[(size_t)(m0 + arow) * Kp + kp0 + 16 + akp];
            avh1 = *(const uint4*)&Ah[(size_t)(m0 + arow) * Kp + kp0 + 16 + akp + 4];
            avl0 = *(const uint4*)&Al[(size_t)(m0 + arow) * Kp + kp0 + 16 + akp];
            avl1 = *(const uint4*)&Al[(size_t)(m0 + arow) * Kp + kp0 + 16 + akp + 4];
            bvh  = *(const uint4*)&Bh[(size_t)(kp0 + 16 + bkp) * N + n0 + bn];
            bvl  = *(const uint4*)&Bl[(size_t)(kp0 + 16 + bkp) * N + n0 + bn];
        }
        __syncthreads();

        #pragma unroll
        for (int kk = 0; kk < 2; kk++) {
            const int kb = kk * 8;
            uint32_t Ah4[2][4], Al4[2][4];
            #pragma unroll
            for (int mt = 0; mt < 2; mt++) {
                const int mr = wm + mt * 16;
                Ah4[mt][0] = ah[mr + gr][kb + tig];
                Ah4[mt][1] = ah[mr + gr + 8][kb + tig];
                Ah4[mt][2] = ah[mr + gr][kb + tig + 4];
                Ah4[mt][3] = ah[mr + gr + 8][kb + tig + 4];
                Al4[mt][0] = al[mr + gr][kb + tig];
                Al4[mt][1] = al[mr + gr + 8][kb + tig];
                Al4[mt][2] = al[mr + gr][kb + tig + 4];
                Al4[mt][3] = al[mr + gr + 8][kb + tig + 4];
            }
            #pragma unroll
            for (int n8 = 0; n8 < 4; n8++) {
                const int col = wn + n8 * 8 + gr;
                uint32_t b0h = bh[kb + tig][col], b1h = bh[kb + tig + 4][col];
                uint32_t b0l = bl[kb + tig][col], b1l = bl[kb + tig + 4][col];
                #pragma unroll
                for (int mt = 0; mt < 2; mt++) {
                    mma16(HH[mt][n8], Ah4[mt], b0h, b1h);
                    mma16(CC[mt][n8], Ah4[mt], b0l, b1l);
                    mma16(CC[mt][n8], Al4[mt], b0h, b1h);
                }
            }
        }
    }

    #pragma unroll
    for (int mt = 0; mt < 2; mt++) {
        const int mr = m0 + wm + mt * 16;
        #pragma unroll
        for (int n8 = 0; n8 < 4; n8++) {
            const int col = n0 + wn + n8 * 8 + 2 * tig;
            const float2 bb = *(const float2*)&bias[col];
            float c0 = HH[mt][n8][0] + CC[mt][n8][0] + bb.x;
            float c1 = HH[mt][n8][1] + CC[mt][n8][1] + bb.y;
            float c2 = HH[mt][n8][2] + CC[mt][n8][2] + bb.x;
            float c3 = HH[mt][n8][3] + CC[mt][n8][3] + bb.y;
            *(float2*)&Cf[(size_t)(mr + gr) * N + col]     = make_float2(c0, c1);
            *(float2*)&Cf[(size_t)(mr + gr + 8) * N + col] = make_float2(c2, c3);
        }
    }
}

// ---------------------------------------------------------------------------
// Merged Q/K/V projection. 128x64 CTA tile, m32xn32 warps. grid (18, 32).
// ---------------------------------------------------------------------------
__global__ __launch_bounds__(256) void gemm_qkv(
    const uint32_t* __restrict__ AhQ, const uint32_t* __restrict__ AlQ,
    const uint32_t* __restrict__ AhK, const uint32_t* __restrict__ AlK,
    const uint32_t* __restrict__ AhV, const uint32_t* __restrict__ AlV,
    const uint32_t* __restrict__ BhQ, const uint32_t* __restrict__ BlQ,
    const float* __restrict__ biasQ,
    const uint32_t* __restrict__ BhK, const uint32_t* __restrict__ BlK,
    const float* __restrict__ biasK,
    const uint32_t* __restrict__ BhV, const uint32_t* __restrict__ BlV,
    const float* __restrict__ biasV,
    uint32_t* __restrict__ Qh, uint32_t* __restrict__ Ql, float qscale,
    uint4* __restrict__ Khl, uint4* __restrict__ Vhl)
{
    __shared__ uint32_t ah[128][20], al[128][20];
    __shared__ uint32_t bh[16][72],  bl[16][72];

    const int sel = blockIdx.x;               // 0..15 Q, 16 K, 17 V
    const int isQ = (sel < 16);
    const uint32_t* Ah = isQ ? AhQ : (sel == 16 ? AhK : AhV);
    const uint32_t* Al = isQ ? AlQ : (sel == 16 ? AlK : AlV);
    const uint32_t* Bh = isQ ? BhQ : (sel == 16 ? BhK : BhV);
    const uint32_t* Bl = isQ ? BlQ : (sel == 16 ? BlK : BlV);
    const float*  bias = isQ ? biasQ : (sel == 16 ? biasK : biasV);
    const int N  = isQ ? 1024 : 64;
    const int n0 = isQ ? sel * 64 : 0;

    const int tid  = threadIdx.x;
    const int warp = tid >> 5;
    const int lane = tid & 31;
    const int gr   = lane >> 2;
    const int tig  = lane & 3;
    const int wm   = (warp & 3) * 32;
    const int wsel = warp >> 2;
    const int wn   = wsel * 32;

    const int m0 = blockIdx.y * 128;
    const int Kp = 512;

    const int arow = tid >> 1;
    const int akp  = (tid & 1) * 8;
    const int bkp  = tid >> 4;
    const int bn   = (tid & 15) * 4;

    float HH[2][4][4], CC[2][4][4];
    #pragma unroll
    for (int mt = 0; mt < 2; mt++)
        #pragma unroll
        for (int n8 = 0; n8 < 4; n8++)
            #pragma unroll
            for (int i = 0; i < 4; i++) { HH[mt][n8][i] = 0.f; CC[mt][n8][i] = 0.f; }

    uint4 avh0 = *(const uint4*)&Ah[(size_t)(m0 + arow) * Kp + akp];
    uint4 avh1 = *(const uint4*)&Ah[(size_t)(m0 + arow) * Kp + akp + 4];
    uint4 avl0 = *(const uint4*)&Al[(size_t)(m0 + arow) * Kp + akp];
    uint4 avl1 = *(const uint4*)&Al[(size_t)(m0 + arow) * Kp + akp + 4];
    uint4 bvh  = *(const uint4*)&Bh[(size_t)bkp * N + n0 + bn];
    uint4 bvl  = *(const uint4*)&Bl[(size_t)bkp * N + n0 + bn];

    for (int kp0 = 0; kp0 < Kp; kp0 += 16) {
        __syncthreads();
        *(uint4*)&ah[arow][akp]     = avh0;
        *(uint4*)&ah[arow][akp + 4] = avh1;
        *(uint4*)&al[arow][akp]     = avl0;
        *(uint4*)&al[arow][akp + 4] = avl1;
        *(uint4*)&bh[bkp][bn] = bvh;
        *(uint4*)&bl[bkp][bn] = bvl;
        if (kp0 + 16 < Kp) {
            avh0 = *(const uint4*)&Ah[(size_t)(m0 + arow) * Kp + kp0 + 16 + akp];
            avh1 = *(const uint4*)&Ah[(size_t)(m0 + arow) * Kp + kp0 + 16 + akp + 4];
            avl0 = *(const uint4*)&Al[(size_t)(m0 + arow) * Kp + kp0 + 16 + akp];
            avl1 = *(const uint4*)&Al[(size_t)(m0 + arow) * Kp + kp0 + 16 + akp + 4];
            bvh  = *(const uint4*)&Bh[(size_t)(kp0 + 16 + bkp) * N + n0 + bn];
            bvl  = *(const uint4*)&Bl[(size_t)(kp0 + 16 + bkp) * N + n0 + bn];
        }
        __syncthreads();

        #pragma unroll
        for (int kk = 0; kk < 2; kk++) {
            const int kb = kk * 8;
            uint32_t Ah4[2][4], Al4[2][4];
            #pragma unroll
            for (int mt = 0; mt < 2; mt++) {
                const int mr = wm + mt * 16;
                Ah4[mt][0] = ah[mr + gr][kb + tig];
                Ah4[mt][1] = ah[mr + gr + 8][kb + tig];
                Ah4[mt][2] = ah[mr + gr][kb + tig + 4];
                Ah4[mt][3] = ah[mr + gr + 8][kb + tig + 4];
                Al4[mt][0] = al[mr + gr][kb + tig];
                Al4[mt][1] = al[mr + gr + 8][kb + tig];
                Al4[mt][2] = al[mr + gr][kb + tig + 4];
                Al4[mt][3] = al[mr + gr + 8][kb + tig + 4];
            }
            #pragma unroll
            for (int n8 = 0; n8 < 4; n8++) {
                const int col = wn + n8 * 8 + gr;
                uint32_t b0h = bh[kb + tig][col], b1h = bh[kb + tig + 4][col];
                uint32_t b0l = bl[kb + tig][col], b1l = bl[kb + tig + 4][col];
                #pragma unroll
                for (int mt = 0; mt < 2; mt++) {
                    mma16(HH[mt][n8], Ah4[mt], b0h, b1h);
                    mma16(CC[mt][n8], Ah4[mt], b0l, b1l);
                    mma16(CC[mt][n8], Al4[mt], b0h, b1h);
                }
            }
        }
    }

    #pragma unroll
    for (int mt = 0; mt < 2; mt++) {
        float R0[4], R1[4], R2[4], R3[4];
        #pragma unroll
        for (int n8 = 0; n8 < 4; n8++) {
            const int col = n0 + wn + n8 * 8 + 2 * tig;
            const float2 bb = *(const float2*)&bias[col];
            R0[n8] = HH[mt][n8][0] + CC[mt][n8][0] + bb.x;
            R1[n8] = HH[mt][n8][1] + CC[mt][n8][1] + bb.y;
            R2[n8] = HH[mt][n8][2] + CC[mt][n8][2] + bb.x;
            R3[n8] = HH[mt][n8][3] + CC[mt][n8][3] + bb.y;
        }
        const int mr = m0 + wm + mt * 16;

        if (isQ) {
            #pragma unroll
            for (int n8 = 0; n8 < 4; n8++) {
                const int col = n0 + wn + n8 * 8 + 2 * tig;
                float c0 = R0[n8] * qscale, c1 = R1[n8] * qscale;
                float c2 = R2[n8] * qscale, c3 = R3[n8] * qscale;
                const int pk = perm8(col >> 1);
                uint32_t H, L;
                split2(c0, c1, H, L);
                Qh[(size_t)(mr + gr) * 512 + pk] = H;
                Ql[(size_t)(mr + gr) * 512 + pk] = L;
                split2(c2, c3, H, L);
                Qh[(size_t)(mr + gr + 8) * 512 + pk] = H;
                Ql[(size_t)(mr + gr + 8) * 512 + pk] = L;
            }
        } else if (sel == 16) {
            uint32_t H[4], L[4], H8[4], L8[4];
            #pragma unroll
            for (int n8 = 0; n8 < 4; n8++) {
                split2(R0[n8], R1[n8], H[n8],  L[n8]);
                split2(R2[n8], R3[n8], H8[n8], L8[n8]);
            }
            const int rg0 = (mr + gr) >> 3;
            const int rg8 = rg0 + 1;
            const int u   = gr * 4 + tig;
            const int kk0 = 2 * wsel;
            Khl[(size_t)(rg0 * 4 + kk0) * 32 + u]     = make_uint4(H[0],  H[1],  L[0],  L[1]);
            Khl[(size_t)(rg0 * 4 + kk0 + 1) * 32 + u] = make_uint4(H[2],  H[3],  L[2],  L[3]);
            Khl[(size_t)(rg8 * 4 + kk0) * 32 + u]     = make_uint4(H8[0], H8[1], L8[0], L8[1]);
            Khl[(size_t)(rg8 * 4 + kk0 + 1) * 32 + u] = make_uint4(H8[2], H8[3], L8[2], L8[3]);
        } else {
            #pragma unroll
            for (int n8 = 0; n8 < 4; n8++) {
                const int col = wn + n8 * 8 + 2 * tig;
                float p0 = __shfl_down_sync(0xffffffffu, R0[n8], 4);
                float p1 = __shfl_down_sync(0xffffffffu, R1[n8], 4);
                float p2 = __shfl_down_sync(0xffffffffu, R2[n8], 4);
                float p3 = __shfl_down_sync(0xffffffffu, R3[n8], 4);
                if ((gr & 1) == 0) {
                    const int ra  = mr + gr;
                    const int b2  = ra >> 11;
                    const int kpa = (ra & 2047) >> 1;
                    const int kpc = kpa >> 3;
                    const int tl  = gr >> 1;
                    uint32_t Ha, La, Hb, Lb;
                    splitf16(R0[n8], p0, Ha, La);
                    splitf16(R2[n8], p2, Hb, Lb);
                    Vhl[((size_t)(b2 * 8 + (col >> 3)) * 128 + kpc) * 32 + (col & 7) * 4 + tl]
                        = make_uint4(Ha, Hb, La, Lb);
                    splitf16(R1[n8], p1, Ha, La);
                    splitf16(R3[n8], p3, Hb, Lb);
                    Vhl[((size_t)(b2 * 8 + (col >> 3)) * 128 + kpc) * 32 + ((col + 1) & 7) * 4 + tl]
                        = make_uint4(Ha, Hb, La, Lb);
                }
            }
        }
    }
}

// ---------------------------------------------------------------------------
// Fused attention (identical to R14). One CTA = (b, h, 32 q-rows).
// ---------------------------------------------------------------------------
#define QR   32
#define PP   1028
#define WSTR 2176

__global__ __launch_bounds__(512, 1) void attn_kernel(
    const uint32_t* __restrict__ qh,  const uint32_t* __restrict__ ql,
    const uint4* __restrict__ khl, const uint4* __restrict__ vhl,
    float* __restrict__ attn, uint32_t* __restrict__ ctxh, uint32_t* __restrict__ ctxl,
    int write_attn)
{
    extern __shared__ uint32_t su[];
    uint32_t* ph = su;
    uint4*    qf = (uint4*)(su + QR * PP);
    float*   red = (float*)((char*)su + 139264);
    float* inv_s = red + 512;

    const int tid  = threadIdx.x;
    const int warp = tid >> 5;
    const int lane = tid & 31;
    const int gr   = lane >> 2;
    const int tig  = lane & 3;

    const int qt = blockIdx.x & 63;
    const int h  = (blockIdx.x >> 6) & (Hc - 1);
    const int b  = blockIdx.x >> 10;
    const int q0 = qt * QR;

    const uint32_t pha = (uint32_t)__cvta_generic_to_shared(ph);

    uint32_t QAh[4][4], QAl[4][4];
    {
        const uint32_t* q0p = &qh[(size_t)(b * Sc + q0 + gr) * 512 + h * 32 + 2 * tig];
        const uint32_t* q8p = q0p + 8 * 512;
        const uint32_t* q0l = &ql[(size_t)(b * Sc + q0 + gr) * 512 + h * 32 + 2 * tig];
        const uint32_t* q8l = q0l + 8 * 512;
        #pragma unroll
        for (int kk = 0; kk < 4; kk++) {
            uint2 a02 = *(const uint2*)&q0p[kk * 8];
            uint2 a13 = *(const uint2*)&q8p[kk * 8];
            QAh[kk][0] = a02.x; QAh[kk][2] = a02.y;
            QAh[kk][1] = a13.x; QAh[kk][3] = a13.y;
            a02 = *(const uint2*)&q0l[kk * 8];
            a13 = *(const uint2*)&q8l[kk * 8];
            QAl[kk][0] = a02.x; QAl[kk][2] = a02.y;
            QAl[kk][1] = a13.x; QAl[kk][3] = a13.y;
        }
    }

    if (warp < 4) {
        const int kk = warp;
        const uint32_t* q0p = &qh[(size_t)(b * Sc + q0 + 16 + gr) * 512 + h * 32 + 2 * tig];
        const uint32_t* q8p = q0p + 8 * 512;
        const uint32_t* q0l = &ql[(size_t)(b * Sc + q0 + 16 + gr) * 512 + h * 32 + 2 * tig];
        const uint32_t* q8l = q0l + 8 * 512;
        uint2 a02 = *(const uint2*)&q0p[kk * 8];
        uint2 a13 = *(const uint2*)&q8p[kk * 8];
        qf[(kk * 2 + 0) * 32 + lane] = make_uint4(a02.x, a13.x, a02.y, a13.y);
        a02 = *(const uint2*)&q0l[kk * 8];
        a13 = *(const uint2*)&q8l[kk * 8];
        qf[(kk * 2 + 1) * 32 + lane] = make_uint4(a02.x, a13.x, a02.y, a13.y);
    }
    __syncthreads();

    float s0 = 0.0f, s1 = 0.0f, s2 = 0.0f, s3 = 0.0f;
    {
        const uint4* kf = khl + ((size_t)(b * 256 + warp) * 4) * 32 + lane;

        #pragma unroll 2
        for (int t = 0; t < 16; t++) {
            const uint4* kt = kf + (size_t)t * 2048;
            float hh0[4] = {0,0,0,0}, hl0[4] = {0,0,0,0}, lh0[4] = {0,0,0,0};
            float hh1[4] = {0,0,0,0}, hl1[4] = {0,0,0,0}, lh1[4] = {0,0,0,0};
            #pragma unroll
            for (int kk = 0; kk < 4; kk++) {
                uint4 kv4 = kt[kk * 32];
                mma16(hh0, QAh[kk], kv4.x, kv4.y);
                mma16(hl0, QAh[kk], kv4.z, kv4.w);
                mma16(lh0, QAl[kk], kv4.x, kv4.y);
                uint4 qh4 = qf[(kk * 2 + 0) * 32 + lane];
                uint4 ql4 = qf[(kk * 2 + 1) * 32 + lane];
                uint32_t Qh1[4] = { qh4.x, qh4.y, qh4.z, qh4.w };
                uint32_t Ql1[4] = { ql4.x, ql4.y, ql4.z, ql4.w };
                mma16(hh1, Qh1, kv4.x, kv4.y);
                mma16(hl1, Qh1, kv4.z, kv4.w);
                mma16(lh1, Ql1, kv4.x, kv4.y);
            }
            float e0 = ex2f((hh0[0] + hl0[0]) + lh0[0]);
            float e1 = ex2f((hh0[1] + hl0[1]) + lh0[1]);
            float e2 = ex2f((hh0[2] + hl0[2]) + lh0[2]);
            float e3 = ex2f((hh0[3] + hl0[3]) + lh0[3]);
            float e4 = ex2f((hh1[0] + hl1[0]) + lh1[0]);
            float e5 = ex2f((hh1[1] + hl1[1]) + lh1[1]);
            float e6 = ex2f((hh1[2] + hl1[2]) + lh1[2]);
            float e7 = ex2f((hh1[3] + hl1[3]) + lh1[3]);
            s0 += e0 + e1;
            s1 += e2 + e3;
            s2 += e4 + e5;
            s3 += e6 + e7;
            const int pc = t * 64 + warp * 4 + tig;
            ph[gr * PP + pc]        = packf16(e0, e1);
            ph[(gr + 8) * PP + pc]  = packf16(e2, e3);
            ph[(gr + 16) * PP + pc] = packf16(e4, e5);
            ph[(gr + 24) * PP + pc] = packf16(e6, e7);
        }
    }

    s0 += __shfl_xor_sync(0xffffffffu, s0, 1);
    s0 += __shfl_xor_sync(0xffffffffu, s0, 2);
    s1 += __shfl_xor_sync(0xffffffffu, s1, 1);
    s1 += __shfl_xor_sync(0xffffffffu, s1, 2);
    s2 += __shfl_xor_sync(0xffffffffu, s2, 1);
    s2 += __shfl_xor_sync(0xffffffffu, s2, 2);
    s3 += __shfl_xor_sync(0xffffffffu, s3, 1);
    s3 += __shfl_xor_sync(0xffffffffu, s3, 2);
    if (tig == 0) {
        red[warp * 32 + gr]      = s0;
        red[warp * 32 + gr + 8]  = s1;
        red[warp * 32 + gr + 16] = s2;
        red[warp * 32 + gr + 24] = s3;
    }
    __syncthreads();

    {
        #pragma unroll
        for (int rr = 0; rr < 2; rr++) {
            const int r = warp * 2 + rr;
            float s = (lane < 16) ? red[lane * 32 + r] : 0.0f;
            #pragma unroll
            for (int o = 16; o; o >>= 1) s += __shfl_xor_sync(0xffffffffu, s, o);
            const float inv = 1.0f / s;
            if (lane == 0) inv_s[r] = inv;

            if (write_attn) {
                const uint32_t* rh = &ph[r * PP];
                size_t base = ((size_t)(b * Hc + h) * Sc + (q0 + r)) * (size_t)Sc;
                #pragma unroll
                for (int c = lane * 4; c < 1024; c += 128) {
                    uint4 h4 = *(const uint4*)&rh[c];
                    float2 p0 = unpackf16(h4.x);
                    float2 p1 = unpackf16(h4.y);
                    float2 p2 = unpackf16(h4.z);
                    float2 p3 = unpackf16(h4.w);
                    __stcs((float4*)&attn[base + 2 * c],
                           make_float4(p0.x * inv, p0.y * inv, p1.x * inv, p1.y * inv));
                    __stcs((float4*)&attn[base + 2 * c + 4],
                           make_float4(p2.x * inv, p2.y * inv, p3.x * inv, p3.y * inv));
                }
            }
        }
    }
    __syncthreads();

    {
        float acc0[8][4], acc1[8][4];
        #pragma unroll
        for (int nt = 0; nt < 8; nt++)
            #pragma unroll
            for (int i = 0; i < 4; i++) { acc0[nt][i] = 0.f; acc1[nt][i] = 0.f; }

        const uint32_t poff = (uint32_t)((((lane & 7) + ((lane >> 3) & 1) * 8) * PP
                                          + ((lane >> 4) & 1) * 4) * 4);
        const uint32_t t1off = (uint32_t)(16 * PP * 4);
        const uint4* vb = vhl + (size_t)(b * 8) * 128 * 32 + lane;

        #pragma unroll 2
        for (int cc = 0; cc < 8; cc++) {
            const int c = warp * 8 + cc;
            uint32_t Pa[4], Pb[4];
            LDSM_X4(Pa[0], Pa[1], Pa[2], Pa[3], pha + poff + (uint32_t)(c * 32));
            LDSM_X4(Pb[0], Pb[1], Pb[2], Pb[3], pha + poff + t1off + (uint32_t)(c * 32));
            #pragma unroll
            for (int nt = 0; nt < 8; nt++) {
                uint4 vv = vb[((size_t)nt * 128 + c) * 32];
                mma16f(acc0[nt], Pa, vv.x, vv.y);
                mma16f(acc0[nt], Pa, vv.z, vv.w);
                mma16f(acc1[nt], Pb, vv.x, vv.y);
                mma16f(acc1[nt], Pb, vv.z, vv.w);
            }
        }

        __syncthreads();

        float* wred = (float*)su + warp * WSTR;
        #pragma unroll
        for (int nt = 0; nt < 8; nt++) {
            const int nc = nt * 8 + 2 * tig;
            *(float2*)&wred[gr * 68 + nc]        = make_float2(acc0[nt][0], acc0[nt][1]);
            *(float2*)&wred[(gr + 8) * 68 + nc]  = make_float2(acc0[nt][2], acc0[nt][3]);
            *(float2*)&wred[(gr + 16) * 68 + nc] = make_float2(acc1[nt][0], acc1[nt][1]);
            *(float2*)&wred[(gr + 24) * 68 + nc] = make_float2(acc1[nt][2], acc1[nt][3]);
        }
        __syncthreads();

        const int e = tid * 4;
        const int q = e >> 6;
        const int n = e & 63;
        float4 s4 = make_float4(0.f, 0.f, 0.f, 0.f);
        const float* rb = (float*)su + q * 68 + n;
        #pragma unroll
        for (int w = 0; w < 16; w++) {
            float4 t4 = *(const float4*)&rb[w * WSTR];
            s4.x += t4.x; s4.y += t4.y; s4.z += t4.z; s4.w += t4.w;
        }
        const float inv = inv_s[q];
        s4.x *= inv; s4.y *= inv; s4.z *= inv; s4.w *= inv;
        uint32_t H, L;
        const size_t row = (size_t)(b * Sc + q0 + q) * 512 + h * 32 + (n >> 1);
        split2(s4.x, s4.y, H, L);
        ctxh[row] = H; ctxl[row] = L;
        split2(s4.z, s4.w, H, L);
        ctxh[row + 1] = H; ctxl[row + 1] = L;
    }
}

// ---------------------------------------------------------------------------
extern "C" void kernel_launch(void* const* d_in, const int* in_sizes, int n_in,
                              void* d_out, int out_size)
{
    const float* query   = (const float*)d_in[0];
    const float* key     = (const float*)d_in[1];
    const float* value   = (const float*)d_in[2];
    const float* wq_w    = (const float*)d_in[3];
    const float* wq_b    = (const float*)d_in[4];
    const float* wk_w    = (const float*)d_in[5];
    const float* wk_b    = (const float*)d_in[6];
    const float* wv_w    = (const float*)d_in[7];
    const float* wv_b    = (const float*)d_in[8];
    const float* dense_w = (const float*)d_in[9];
    const float* dense_b = (const float*)d_in[10];

    float* out = (float*)d_out;
    const long long OUT = (long long)Bc * Sc * HIDc;
    const long long ATT = (long long)Bc * Hc * Sc * Sc;
    const int write_attn = ((long long)out_size >= OUT + ATT) ? 1 : 0;
    float* attn = out + OUT;

    uint32_t *inqh, *inql, *inkh, *inkl, *invh, *invl;
    uint32_t *wqh, *wql, *wkh, *wkl, *wvh, *wvl, *dwh, *dwl;
    uint32_t *qh, *ql, *ctxh, *ctxl;
    uint4 *khl, *vhl;
    cudaGetSymbolAddress((void**)&inqh, g_inqh);
    cudaGetSymbolAddress((void**)&inql, g_inql);
    cudaGetSymbolAddress((void**)&inkh, g_inkh);
    cudaGetSymbolAddress((void**)&inkl, g_inkl);
    cudaGetSymbolAddress((void**)&invh, g_invh);
    cudaGetSymbolAddress((void**)&invl, g_invl);
    cudaGetSymbolAddress((void**)&wqh, g_wqh);
    cudaGetSymbolAddress((void**)&wql, g_wql);
    cudaGetSymbolAddress((void**)&wkh, g_wkh);
    cudaGetSymbolAddress((void**)&wkl, g_wkl);
    cudaGetSymbolAddress((void**)&wvh, g_wvh);
    cudaGetSymbolAddress((void**)&wvl, g_wvl);
    cudaGetSymbolAddress((void**)&dwh, g_dwh);
    cudaGetSymbolAddress((void**)&dwl, g_dwl);
    cudaGetSymbolAddress((void**)&qh, g_qh);
    cudaGetSymbolAddress((void**)&ql, g_ql);
    cudaGetSymbolAddress((void**)&khl, g_khl);
    cudaGetSymbolAddress((void**)&vhl, g_vhl);
    cudaGetSymbolAddress((void**)&ctxh, g_ctxh);
    cudaGetSymbolAddress((void**)&ctxl, g_ctxl);

    const int M = Bc * Sc;  // 4096

    // launch #0: all packing
    const int NPK = 3 * NIN + 2 * NWQ + 2 * NWK;
    pack_all<<<(NPK + 255) / 256, 256>>>(query, key, value, wq_w, wk_w, wv_w, dense_w,
                                         inqh, inql, inkh, inkl, invh, invl,
                                         wqh, wql, wkh, wkl, wvh, wvl, dwh, dwl);

    // launch #1: merged q/k/v projections (128x64 tiles)
    const float QSCALE = 0.125f * 1.4426950408889634f;
    gemm_qkv<<<dim3(18, 32), 256>>>(inqh, inql, inkh, inkl, invh, invl,
                                    wqh, wql, wq_b, wkh, wkl, wk_b, wvh, wvl, wv_b,
                                    qh, ql, QSCALE, khl, vhl);

    // launch #2: fused attention (R14 version)
    const int smem = 139264 + (512 + 32) * 4;  // 141,440 B
    cudaFuncSetAttribute(attn_kernel, cudaFuncAttributeMaxDynamicSharedMemorySize, smem);
    attn_kernel<<<Bc * Hc * (Sc / QR), 512, smem>>>(qh, ql, khl, vhl,
                                                    attn, ctxh, ctxl, write_attn);

    // launch #3: output projection (128x64 tiles)
    gemm_pk<<<dim3(16, 32), 256>>>(ctxh, ctxl, dwh, dwl, dense_b, out, M, HIDc, HIDc);
}

// round 17
// speedup vs baseline: 1.1714x; 1.1130x over previous
#include <cuda_runtime.h>
#include <math.h>
#include <stdint.h>

#define Bc   2
#define Sc   2048
#define HIDc 1024
#define Hc   16
#define Dc   64

// ---------------------------------------------------------------------------
// Device scratch
// ---------------------------------------------------------------------------
__device__ uint32_t g_inqh[4096 * 512], g_inql[4096 * 512];
__device__ uint32_t g_inkh[4096 * 512], g_inkl[4096 * 512];
__device__ uint32_t g_invh[4096 * 512], g_invl[4096 * 512];
__device__ uint32_t g_wqh[512 * 1024], g_wql[512 * 1024];
__device__ uint32_t g_wkh[512 * 64],   g_wkl[512 * 64];
__device__ uint32_t g_wvh[512 * 64],   g_wvl[512 * 64];
__device__ uint32_t g_dwh[512 * 1024];                      // single f16 pairs
__device__ uint32_t g_qh[4096 * 512],  g_ql[4096 * 512];
__device__ uint4 g_khl[512 * 4 * 32];
__device__ uint4 g_vhl[16 * 128 * 32];
__device__ uint32_t g_ctxh[4096 * 512], g_ctxl[4096 * 512]; // split-f16

// ---------------------------------------------------------------------------
// helpers
// ---------------------------------------------------------------------------
__device__ __forceinline__ uint32_t packbf(float x0, float x1) {
    uint32_t r;
    asm("cvt.rn.bf16x2.f32 %0, %1, %2;" : "=r"(r) : "f"(x1), "f"(x0));
    return r;
}
__device__ __forceinline__ float blo(uint32_t u) { return __uint_as_float(u << 16); }
__device__ __forceinline__ float bhi(uint32_t u) { return __uint_as_float(u & 0xffff0000u); }

__device__ __forceinline__ void split2(float x0, float x1, uint32_t& h, uint32_t& l) {
    h = packbf(x0, x1);
    l = packbf(x0 - blo(h), x1 - bhi(h));
}

__device__ __forceinline__ uint32_t packf16(float x0, float x1) {
    uint32_t r;
    asm("cvt.rn.f16x2.f32 %0, %1, %2;" : "=r"(r) : "f"(x1), "f"(x0));
    return r;
}
__device__ __forceinline__ float2 unpackf16(uint32_t u) {
    float lo, hi;
    asm("{.reg .f16 l, h;\n\t"
        " mov.b32 {l, h}, %2;\n\t"
        " cvt.f32.f16 %0, l;\n\t"
        " cvt.f32.f16 %1, h;}"
        : "=f"(lo), "=f"(hi) : "r"(u));
    return make_float2(lo, hi);
}
__device__ __forceinline__ void splitf16(float x0, float x1, uint32_t& h, uint32_t& l) {
    h = packf16(x0, x1);
    float2 r = unpackf16(h);
    l = packf16(x0 - r.x, x1 - r.y);
}

__device__ __forceinline__ void mma16(float* d, const uint32_t* a, uint32_t b0, uint32_t b1) {
    asm volatile(
        "mma.sync.aligned.m16n8k16.row.col.f32.bf16.bf16.f32 "
        "{%0,%1,%2,%3}, {%4,%5,%6,%7}, {%8,%9}, {%0,%1,%2,%3};"
        : "+f"(d[0]), "+f"(d[1]), "+f"(d[2]), "+f"(d[3])
        : "r"(a[0]), "r"(a[1]), "r"(a[2]), "r"(a[3]), "r"(b0), "r"(b1));
}
__device__ __forceinline__ void mma16f(float* d, const uint32_t* a, uint32_t b0, uint32_t b1) {
    asm volatile(
        "mma.sync.aligned.m16n8k16.row.col.f32.f16.f16.f32 "
        "{%0,%1,%2,%3}, {%4,%5,%6,%7}, {%8,%9}, {%0,%1,%2,%3};"
        : "+f"(d[0]), "+f"(d[1]), "+f"(d[2]), "+f"(d[3])
        : "r"(a[0]), "r"(a[1]), "r"(a[2]), "r"(a[3]), "r"(b0), "r"(b1));
}

#define LDSM_X4(r0, r1, r2, r3, addr) \
    asm volatile("ldmatrix.sync.aligned.m8n8.x4.shared.b16 {%0,%1,%2,%3}, [%4];" \
                 : "=r"(r0), "=r"(r1), "=r"(r2), "=r"(r3) : "r"(addr))

__device__ __forceinline__ float ex2f(float x) {
    float r;
    asm("ex2.approx.f32 %0, %1;" : "=f"(r) : "f"(x));
    return r;
}

__device__ __forceinline__ int perm8(int kp) {
    int w = kp & 7;
    return (kp & ~7) | ((w < 4) ? (2 * w) : (2 * (w - 4) + 1));
}

// ---------------------------------------------------------------------------
// Mega-pack (dense weights -> single f16 pairs)
// ---------------------------------------------------------------------------
#define NIN  (4096 * 512)
#define NWQ  (512 * 1024)
#define NWK  (512 * 64)

__global__ void pack_all(
    const float* __restrict__ q,  const float* __restrict__ k,  const float* __restrict__ v,
    const float* __restrict__ wq, const float* __restrict__ wk, const float* __restrict__ wv,
    const float* __restrict__ dw,
    uint32_t* __restrict__ qh, uint32_t* __restrict__ ql,
    uint32_t* __restrict__ kh, uint32_t* __restrict__ kl,
    uint32_t* __restrict__ vh, uint32_t* __restrict__ vl,
    uint32_t* __restrict__ wqh, uint32_t* __restrict__ wql,
    uint32_t* __restrict__ wkh, uint32_t* __restrict__ wkl,
    uint32_t* __restrict__ wvh, uint32_t* __restrict__ wvl,
    uint32_t* __restrict__ dwh)
{
    int i = blockIdx.x * blockDim.x + threadIdx.x;
    uint32_t h, l;
    if (i < NIN) {
        float2 t = *(const float2*)&q[2 * i];
        split2(t.x, t.y, h, l); qh[i] = h; ql[i] = l; return;
    }
    i -= NIN;
    if (i < NIN) {
        float2 t = *(const float2*)&k[2 * i];
        split2(t.x, t.y, h, l); kh[i] = h; kl[i] = l; return;
    }
    i -= NIN;
    if (i < NIN) {
        float2 t = *(const float2*)&v[2 * i];
        split2(t.x, t.y, h, l); vh[i] = h; vl[i] = l; return;
    }
    i -= NIN;
    if (i < NWQ) {
        int rp = i >> 10, c = i & 1023;
        split2(wq[(size_t)(2 * rp) * 1024 + c], wq[(size_t)(2 * rp + 1) * 1024 + c], h, l);
        wqh[i] = h; wql[i] = l; return;
    }
    i -= NWQ;
    if (i < NWQ) {
        int rp = i >> 10, c = i & 1023;
        dwh[i] = packf16(dw[(size_t)(2 * rp) * 1024 + c], dw[(size_t)(2 * rp + 1) * 1024 + c]);
        return;
    }
    i -= NWQ;
    if (i < NWK) {
        int rp = i >> 6, c = i & 63;
        split2(wk[(size_t)(2 * rp) * 64 + c], wk[(size_t)(2 * rp + 1) * 64 + c], h, l);
        wkh[i] = h; wkl[i] = l; return;
    }
    i -= NWK;
    if (i < NWK) {
        int rp = i >> 6, c = i & 63;
        split2(wv[(size_t)(2 * rp) * 64 + c], wv[(size_t)(2 * rp + 1) * 64 + c], h, l);
        wvh[i] = h; wvl[i] = l; return;
    }
}

// ---------------------------------------------------------------------------
// Dense GEMM (f16): A = ctx split-f16 2-term, B = weights single f16.
// 64x64 tile, k-chunk 32. 16 LDS + 8 MMA per k16 per warp.
// ---------------------------------------------------------------------------
__global__ __launch_bounds__(256) void gemm_dense(
    const uint32_t* __restrict__ Ah, const uint32_t* __restrict__ Al,
    const uint32_t* __restrict__ Bh,
    const float* __restrict__ bias, float* __restrict__ Cf,
    int M, int N, int K)
{
    __shared__ uint32_t ah[64][20], al[64][20];
    __shared__ uint32_t bh[16][72];

    const int tid  = threadIdx.x;
    const int warp = tid >> 5;
    const int lane = tid & 31;
    const int gr   = lane >> 2;
    const int tig  = lane & 3;
    const int wm   = (warp & 3) * 16;
    const int wn   = (warp >> 2) * 32;

    const int m0 = blockIdx.y * 64;
    const int n0 = blockIdx.x * 64;
    const int Kp = K >> 1;

    const int arow = tid >> 2;
    const int akp  = (tid & 3) * 4;
    const int bkp  = tid >> 4;
    const int bn   = (tid & 15) * 4;

    float HH[4][4], CC[4][4];
    #pragma unroll
    for (int n8 = 0; n8 < 4; n8++)
        #pragma unroll
        for (int i = 0; i < 4; i++) { HH[n8][i] = 0.f; CC[n8][i] = 0.f; }

    uint4 avh = *(const uint4*)&Ah[(size_t)(m0 + arow) * Kp + akp];
    uint4 avl = *(const uint4*)&Al[(size_t)(m0 + arow) * Kp + akp];
    uint4 bvh = *(const uint4*)&Bh[(size_t)bkp * N + n0 + bn];

    for (int kp0 = 0; kp0 < Kp; kp0 += 16) {
        __syncthreads();
        *(uint4*)&ah[arow][akp] = avh;
        *(uint4*)&al[arow][akp] = avl;
        *(uint4*)&bh[bkp][bn] = bvh;
        if (kp0 + 16 < Kp) {
            avh = *(const uint4*)&Ah[(size_t)(m0 + arow) * Kp + kp0 + 16 + akp];
            avl = *(const uint4*)&Al[(size_t)(m0 + arow) * Kp + kp0 + 16 + akp];
            bvh = *(const uint4*)&Bh[(size_t)(kp0 + 16 + bkp) * N + n0 + bn];
        }
        __syncthreads();

        #pragma unroll
        for (int kk = 0; kk < 2; kk++) {
            const int kb = kk * 8;
            uint32_t Ah4[4] = { ah[wm + gr][kb + tig],     ah[wm + gr + 8][kb + tig],
                                ah[wm + gr][kb + tig + 4], ah[wm + gr + 8][kb + tig + 4] };
            uint32_t Al4[4] = { al[wm + gr][kb + tig],     al[wm + gr + 8][kb + tig],
                                al[wm + gr][kb + tig + 4], al[wm + gr + 8][kb + tig + 4] };
            #pragma unroll
            for (int n8 = 0; n8 < 4; n8++) {
                const int col = wn + n8 * 8 + gr;
                uint32_t b0 = bh[kb + tig][col], b1 = bh[kb + tig + 4][col];
                mma16f(HH[n8], Ah4, b0, b1);
                mma16f(CC[n8], Al4, b0, b1);
            }
        }
    }

    #pragma unroll
    for (int n8 = 0; n8 < 4; n8++) {
        const int col = n0 + wn + n8 * 8 + 2 * tig;
        const float2 bb = *(const float2*)&bias[col];
        float c0 = HH[n8][0] + CC[n8][0] + bb.x;
        float c1 = HH[n8][1] + CC[n8][1] + bb.y;
        float c2 = HH[n8][2] + CC[n8][2] + bb.x;
        float c3 = HH[n8][3] + CC[n8][3] + bb.y;
        *(float2*)&Cf[(size_t)(m0 + wm + gr) * N + col]     = make_float2(c0, c1);
        *(float2*)&Cf[(size_t)(m0 + wm + gr + 8) * N + col] = make_float2(c2, c3);
    }
}

// ---------------------------------------------------------------------------
// Merged Q/K/V projection (exact R14 version). grid (18, 64).
// ---------------------------------------------------------------------------
__global__ __launch_bounds__(256) void gemm_qkv(
    const uint32_t* __restrict__ AhQ, const uint32_t* __restrict__ AlQ,
    const uint32_t* __restrict__ AhK, const uint32_t* __restrict__ AlK,
    const uint32_t* __restrict__ AhV, const uint32_t* __restrict__ AlV,
    const uint32_t* __restrict__ BhQ, const uint32_t* __restrict__ BlQ,
    const float* __restrict__ biasQ,
    const uint32_t* __restrict__ BhK, const uint32_t* __restrict__ BlK,
    const float* __restrict__ biasK,
    const uint32_t* __restrict__ BhV, const uint32_t* __restrict__ BlV,
    const float* __restrict__ biasV,
    uint32_t* __restrict__ Qh, uint32_t* __restrict__ Ql, float qscale,
    uint4* __restrict__ Khl, uint4* __restrict__ Vhl)
{
    __shared__ uint32_t ah[64][20], al[64][20];
    __shared__ uint32_t bh[16][72], bl[16][72];

    const int sel = blockIdx.x;
    const int isQ = (sel < 16);
    const uint32_t* Ah = isQ ? AhQ : (sel == 16 ? AhK : AhV);
    const uint32_t* Al = isQ ? AlQ : (sel == 16 ? AlK : AlV);
    const uint32_t* Bh = isQ ? BhQ : (sel == 16 ? BhK : BhV);
    const uint32_t* Bl = isQ ? BlQ : (sel == 16 ? BlK : BlV);
    const float*  bias = isQ ? biasQ : (sel == 16 ? biasK : biasV);
    const int N  = isQ ? 1024 : 64;
    const int n0 = isQ ? sel * 64 : 0;

    const int tid  = threadIdx.x;
    const int warp = tid >> 5;
    const int lane = tid & 31;
    const int gr   = lane >> 2;
    const int tig  = lane & 3;
    const int wm   = (warp & 3) * 16;
    const int wsel = warp >> 2;
    const int wn   = wsel * 32;

    const int m0 = blockIdx.y * 64;
    const int Kp = 512;

    const int arow = tid >> 2;
    const int akp  = (tid & 3) * 4;
    const int bkp  = tid >> 4;
    const int bn   = (tid & 15) * 4;

    float HH[4][4], HL[4][4], LH[4][4];
    #pragma unroll
    for (int n8 = 0; n8 < 4; n8++)
        #pragma unroll
        for (int i = 0; i < 4; i++) { HH[n8][i] = 0.f; HL[n8][i] = 0.f; LH[n8][i] = 0.f; }

    uint4 avh = *(const uint4*)&Ah[(size_t)(m0 + arow) * Kp + akp];
    uint4 avl = *(const uint4*)&Al[(size_t)(m0 + arow) * Kp + akp];
    uint4 bvh = *(const uint4*)&Bh[(size_t)bkp * N + n0 + bn];
    uint4 bvl = *(const uint4*)&Bl[(size_t)bkp * N + n0 + bn];

    for (int kp0 = 0; kp0 < Kp; kp0 += 16) {
        __syncthreads();
        *(uint4*)&ah[arow][akp] = avh;
        *(uint4*)&al[arow][akp] = avl;
        *(uint4*)&bh[bkp][bn] = bvh;
        *(uint4*)&bl[bkp][bn] = bvl;
        if (kp0 + 16 < Kp) {
            avh = *(const uint4*)&Ah[(size_t)(m0 + arow) * Kp + kp0 + 16 + akp];
            avl = *(const uint4*)&Al[(size_t)(m0 + arow) * Kp + kp0 + 16 + akp];
            bvh = *(const uint4*)&Bh[(size_t)(kp0 + 16 + bkp) * N + n0 + bn];
            bvl = *(const uint4*)&Bl[(size_t)(kp0 + 16 + bkp) * N + n0 + bn];
        }
        __syncthreads();

        #pragma unroll
        for (int kk = 0; kk < 2; kk++) {
            const int kb = kk * 8;
            uint32_t Ah4[4] = { ah[wm + gr][kb + tig],     ah[wm + gr + 8][kb + tig],
                                ah[wm + gr][kb + tig + 4], ah[wm + gr + 8][kb + tig + 4] };
            uint32_t Al4[4] = { al[wm + gr][kb + tig],     al[wm + gr + 8][kb + tig],
                                al[wm + gr][kb + tig + 4], al[wm + gr + 8][kb + tig + 4] };
            #pragma unroll
            for (int n8 = 0; n8 < 4; n8++) {
                const int col = wn + n8 * 8 + gr;
                uint32_t b0h = bh[kb + tig][col], b1h = bh[kb + tig + 4][col];
                uint32_t b0l = bl[kb + tig][col], b1l = bl[kb + tig + 4][col];
                mma16(HH[n8], Ah4, b0h, b1h);
                mma16(HL[n8], Ah4, b0l, b1l);
                mma16(LH[n8], Al4, b0h, b1h);
            }
        }
    }

    float R0[4], R1[4], R2[4], R3[4];
    #pragma unroll
    for (int n8 = 0; n8 < 4; n8++) {
        const int col = n0 + wn + n8 * 8 + 2 * tig;
        const float2 bb = *(const float2*)&bias[col];
        R0[n8] = (HH[n8][0] + HL[n8][0]) + LH[n8][0] + bb.x;
        R1[n8] = (HH[n8][1] + HL[n8][1]) + LH[n8][1] + bb.y;
        R2[n8] = (HH[n8][2] + HL[n8][2]) + LH[n8][2] + bb.x;
        R3[n8] = (HH[n8][3] + HL[n8][3]) + LH[n8][3] + bb.y;
    }

    if (isQ) {
        #pragma unroll
        for (int n8 = 0; n8 < 4; n8++) {
            const int col = n0 + wn + n8 * 8 + 2 * tig;
            float c0 = R0[n8] * qscale, c1 = R1[n8] * qscale;
            float c2 = R2[n8] * qscale, c3 = R3[n8] * qscale;
            const int pk = perm8(col >> 1);
            uint32_t H, L;
            split2(c0, c1, H, L);
            Qh[(size_t)(m0 + wm + gr) * 512 + pk] = H;
            Ql[(size_t)(m0 + wm + gr) * 512 + pk] = L;
            split2(c2, c3, H, L);
            Qh[(size_t)(m0 + wm + gr + 8) * 512 + pk] = H;
            Ql[(size_t)(m0 + wm + gr + 8) * 512 + pk] = L;
        }
    } else if (sel == 16) {
        uint32_t H[4], L[4], H8[4], L8[4];
        #pragma unroll
        for (int n8 = 0; n8 < 4; n8++) {
            split2(R0[n8], R1[n8], H[n8],  L[n8]);
            split2(R2[n8], R3[n8], H8[n8], L8[n8]);
        }
        const int rg0 = (m0 + wm + gr) >> 3;
        const int rg8 = rg0 + 1;
        const int u   = gr * 4 + tig;
        const int kk0 = 2 * wsel;
        Khl[(size_t)(rg0 * 4 + kk0) * 32 + u]     = make_uint4(H[0],  H[1],  L[0],  L[1]);
        Khl[(size_t)(rg0 * 4 + kk0 + 1) * 32 + u] = make_uint4(H[2],  H[3],  L[2],  L[3]);
        Khl[(size_t)(rg8 * 4 + kk0) * 32 + u]     = make_uint4(H8[0], H8[1], L8[0], L8[1]);
        Khl[(size_t)(rg8 * 4 + kk0 + 1) * 32 + u] = make_uint4(H8[2], H8[3], L8[2], L8[3]);
    } else {
        #pragma unroll
        for (int n8 = 0; n8 < 4; n8++) {
            const int col = wn + n8 * 8 + 2 * tig;
            float p0 = __shfl_down_sync(0xffffffffu, R0[n8], 4);
            float p1 = __shfl_down_sync(0xffffffffu, R1[n8], 4);
            float p2 = __shfl_down_sync(0xffffffffu, R2[n8], 4);
            float p3 = __shfl_down_sync(0xffffffffu, R3[n8], 4);
            if ((gr & 1) == 0) {
                const int ra  = m0 + wm + gr;
                const int b2  = ra >> 11;
                const int kpa = (ra & 2047) >> 1;
                const int kpc = kpa >> 3;
                const int tl  = gr >> 1;
                uint32_t Ha, La, Hb, Lb;
                splitf16(R0[n8], p0, Ha, La);
                splitf16(R2[n8], p2, Hb, Lb);
                Vhl[((size_t)(b2 * 8 + (col >> 3)) * 128 + kpc) * 32 + (col & 7) * 4 + tl]
                    = make_uint4(Ha, Hb, La, Lb);
                splitf16(R1[n8], p1, Ha, La);
                splitf16(R3[n8], p3, Hb, Lb);
                Vhl[((size_t)(b2 * 8 + (col >> 3)) * 128 + kpc) * 32 + ((col + 1) & 7) * 4 + tl]
                    = make_uint4(Ha, Hb, La, Lb);
            }
        }
    }
}

// ---------------------------------------------------------------------------
// Fused attention (R14 version; ctx written as split-f16).
// ---------------------------------------------------------------------------
#define QR   32
#define PP   1028
#define WSTR 2176

__global__ __launch_bounds__(512, 1) void attn_kernel(
    const uint32_t* __restrict__ qh,  const uint32_t* __restrict__ ql,
    const uint4* __restrict__ khl, const uint4* __restrict__ vhl,
    float* __restrict__ attn, uint32_t* __restrict__ ctxh, uint32_t* __restrict__ ctxl,
    int write_attn)
{
    extern __shared__ uint32_t su[];
    uint32_t* ph = su;
    uint4*    qf = (uint4*)(su + QR * PP);
    float*   red = (float*)((char*)su + 139264);
    float* inv_s = red + 512;

    const int tid  = threadIdx.x;
    const int warp = tid >> 5;
    const int lane = tid & 31;
    const int gr   = lane >> 2;
    const int tig  = lane & 3;

    const int qt = blockIdx.x & 63;
    const int h  = (blockIdx.x >> 6) & (Hc - 1);
    const int b  = blockIdx.x >> 10;
    const int q0 = qt * QR;

    const uint32_t pha = (uint32_t)__cvta_generic_to_shared(ph);

    uint32_t QAh[4][4], QAl[4][4];
    {
        const uint32_t* q0p = &qh[(size_t)(b * Sc + q0 + gr) * 512 + h * 32 + 2 * tig];
        const uint32_t* q8p = q0p + 8 * 512;
        const uint32_t* q0l = &ql[(size_t)(b * Sc + q0 + gr) * 512 + h * 32 + 2 * tig];
        const uint32_t* q8l = q0l + 8 * 512;
        #pragma unroll
        for (int kk = 0; kk < 4; kk++) {
            uint2 a02 = *(const uint2*)&q0p[kk * 8];
            uint2 a13 = *(const uint2*)&q8p[kk * 8];
            QAh[kk][0] = a02.x; QAh[kk][2] = a02.y;
            QAh[kk][1] = a13.x; QAh[kk][3] = a13.y;
            a02 = *(const uint2*)&q0l[kk * 8];
            a13 = *(const uint2*)&q8l[kk * 8];
            QAl[kk][0] = a02.x; QAl[kk][2] = a02.y;
            QAl[kk][1] = a13.x; QAl[kk][3] = a13.y;
        }
    }

    if (warp < 4) {
        const int kk = warp;
        const uint32_t* q0p = &qh[(size_t)(b * Sc + q0 + 16 + gr) * 512 + h * 32 + 2 * tig];
        const uint32_t* q8p = q0p + 8 * 512;
        const uint32_t* q0l = &ql[(size_t)(b * Sc + q0 + 16 + gr) * 512 + h * 32 + 2 * tig];
        const uint32_t* q8l = q0l + 8 * 512;
        uint2 a02 = *(const uint2*)&q0p[kk * 8];
        uint2 a13 = *(const uint2*)&q8p[kk * 8];
        qf[(kk * 2 + 0) * 32 + lane] = make_uint4(a02.x, a13.x, a02.y, a13.y);
        a02 = *(const uint2*)&q0l[kk * 8];
        a13 = *(const uint2*)&q8l[kk * 8];
        qf[(kk * 2 + 1) * 32 + lane] = make_uint4(a02.x, a13.x, a02.y, a13.y);
    }
    __syncthreads();

    float s0 = 0.0f, s1 = 0.0f, s2 = 0.0f, s3 = 0.0f;
    {
        const uint4* kf = khl + ((size_t)(b * 256 + warp) * 4) * 32 + lane;

        #pragma unroll 2
        for (int t = 0; t < 16; t++) {
            const uint4* kt = kf + (size_t)t * 2048;
            float hh0[4] = {0,0,0,0}, hl0[4] = {0,0,0,0}, lh0[4] = {0,0,0,0};
            float hh1[4] = {0,0,0,0}, hl1[4] = {0,0,0,0}, lh1[4] = {0,0,0,0};
            #pragma unroll
            for (int kk = 0; kk < 4; kk++) {
                uint4 kv4 = kt[kk * 32];
                mma16(hh0, QAh[kk], kv4.x, kv4.y);
                mma16(hl0, QAh[kk], kv4.z, kv4.w);
                mma16(lh0, QAl[kk], kv4.x, kv4.y);
                uint4 qh4 = qf[(kk * 2 + 0) * 32 + lane];
                uint4 ql4 = qf[(kk * 2 + 1) * 32 + lane];
                uint32_t Qh1[4] = { qh4.x, qh4.y, qh4.z, qh4.w };
                uint32_t Ql1[4] = { ql4.x, ql4.y, ql4.z, ql4.w };
                mma16(hh1, Qh1, kv4.x, kv4.y);
                mma16(hl1, Qh1, kv4.z, kv4.w);
                mma16(lh1, Ql1, kv4.x, kv4.y);
            }
            float e0 = ex2f((hh0[0] + hl0[0]) + lh0[0]);
            float e1 = ex2f((hh0[1] + hl0[1]) + lh0[1]);
            float e2 = ex2f((hh0[2] + hl0[2]) + lh0[2]);
            float e3 = ex2f((hh0[3] + hl0[3]) + lh0[3]);
            float e4 = ex2f((hh1[0] + hl1[0]) + lh1[0]);
            float e5 = ex2f((hh1[1] + hl1[1]) + lh1[1]);
            float e6 = ex2f((hh1[2] + hl1[2]) + lh1[2]);
            float e7 = ex2f((hh1[3] + hl1[3]) + lh1[3]);
            s0 += e0 + e1;
            s1 += e2 + e3;
            s2 += e4 + e5;
            s3 += e6 + e7;
            const int pc = t * 64 + warp * 4 + tig;
            ph[gr * PP + pc]        = packf16(e0, e1);
            ph[(gr + 8) * PP + pc]  = packf16(e2, e3);
            ph[(gr + 16) * PP + pc] = packf16(e4, e5);
            ph[(gr + 24) * PP + pc] = packf16(e6, e7);
        }
    }

    s0 += __shfl_xor_sync(0xffffffffu, s0, 1);
    s0 += __shfl_xor_sync(0xffffffffu, s0, 2);
    s1 += __shfl_xor_sync(0xffffffffu, s1, 1);
    s1 += __shfl_xor_sync(0xffffffffu, s1, 2);
    s2 += __shfl_xor_sync(0xffffffffu, s2, 1);
    s2 += __shfl_xor_sync(0xffffffffu, s2, 2);
    s3 += __shfl_xor_sync(0xffffffffu, s3, 1);
    s3 += __shfl_xor_sync(0xffffffffu, s3, 2);
    if (tig == 0) {
        red[warp * 32 + gr]      = s0;
        red[warp * 32 + gr + 8]  = s1;
        red[warp * 32 + gr + 16] = s2;
        red[warp * 32 + gr + 24] = s3;
    }
    __syncthreads();

    {
        #pragma unroll
        for (int rr = 0; rr < 2; rr++) {
            const int r = warp * 2 + rr;
            float s = (lane < 16) ? red[lane * 32 + r] : 0.0f;
            #pragma unroll
            for (int o = 16; o; o >>= 1) s += __shfl_xor_sync(0xffffffffu, s, o);
            const float inv = 1.0f / s;
            if (lane == 0) inv_s[r] = inv;

            if (write_attn) {
                const uint32_t* rh = &ph[r * PP];
                size_t base = ((size_t)(b * Hc + h) * Sc + (q0 + r)) * (size_t)Sc;
                #pragma unroll
                for (int c = lane * 4; c < 1024; c += 128) {
                    uint4 h4 = *(const uint4*)&rh[c];
                    float2 p0 = unpackf16(h4.x);
                    float2 p1 = unpackf16(h4.y);
                    float2 p2 = unpackf16(h4.z);
                    float2 p3 = unpackf16(h4.w);
                    __stcs((float4*)&attn[base + 2 * c],
                           make_float4(p0.x * inv, p0.y * inv, p1.x * inv, p1.y * inv));
                    __stcs((float4*)&attn[base + 2 * c + 4],
                           make_float4(p2.x * inv, p2.y * inv, p3.x * inv, p3.y * inv));
                }
            }
        }
    }
    __syncthreads();

    {
        float acc0[8][4], acc1[8][4];
        #pragma unroll
        for (int nt = 0; nt < 8; nt++)
            #pragma unroll
            for (int i = 0; i < 4; i++) { acc0[nt][i] = 0.f; acc1[nt][i] = 0.f; }

        const uint32_t poff = (uint32_t)((((lane & 7) + ((lane >> 3) & 1) * 8) * PP
                                          + ((lane >> 4) & 1) * 4) * 4);
        const uint32_t t1off = (uint32_t)(16 * PP * 4);
        const uint4* vb = vhl + (size_t)(b * 8) * 128 * 32 + lane;

        #pragma unroll 2
        for (int cc = 0; cc < 8; cc++) {
            const int c = warp * 8 + cc;
            uint32_t Pa[4], Pb[4];
            LDSM_X4(Pa[0], Pa[1], Pa[2], Pa[3], pha + poff + (uint32_t)(c * 32));
            LDSM_X4(Pb[0], Pb[1], Pb[2], Pb[3], pha + poff + t1off + (uint32_t)(c * 32));
            #pragma unroll
            for (int nt = 0; nt < 8; nt++) {
                uint4 vv = vb[((size_t)nt * 128 + c) * 32];
                mma16f(acc0[nt], Pa, vv.x, vv.y);
                mma16f(acc0[nt], Pa, vv.z, vv.w);
                mma16f(acc1[nt], Pb, vv.x, vv.y);
                mma16f(acc1[nt], Pb, vv.z, vv.w);
            }
        }

        __syncthreads();

        float* wred = (float*)su + warp * WSTR;
        #pragma unroll
        for (int nt = 0; nt < 8; nt++) {
            const int nc = nt * 8 + 2 * tig;
            *(float2*)&wred[gr * 68 + nc]        = make_float2(acc0[nt][0], acc0[nt][1]);
            *(float2*)&wred[(gr + 8) * 68 + nc]  = make_float2(acc0[nt][2], acc0[nt][3]);
            *(float2*)&wred[(gr + 16) * 68 + nc] = make_float2(acc1[nt][0], acc1[nt][1]);
            *(float2*)&wred[(gr + 24) * 68 + nc] = make_float2(acc1[nt][2], acc1[nt][3]);
        }
        __syncthreads();

        const int e = tid * 4;
        const int q = e >> 6;
        const int n = e & 63;
        float4 s4 = make_float4(0.f, 0.f, 0.f, 0.f);
        const float* rb = (float*)su + q * 68 + n;
        #pragma unroll
        for (int w = 0; w < 16; w++) {
            float4 t4 = *(const float4*)&rb[w * WSTR];
            s4.x += t4.x; s4.y += t4.y; s4.z += t4.z; s4.w += t4.w;
        }
        const float inv = inv_s[q];
        s4.x *= inv; s4.y *= inv; s4.z *= inv; s4.w *= inv;
        uint32_t H, L;
        const size_t row = (size_t)(b * Sc + q0 + q) * 512 + h * 32 + (n >> 1);
        splitf16(s4.x, s4.y, H, L);
        ctxh[row] = H; ctxl[row] = L;
        splitf16(s4.z, s4.w, H, L);
        ctxh[row + 1] = H; ctxl[row + 1] = L;
    }
}

// ---------------------------------------------------------------------------
extern "C" void kernel_launch(void* const* d_in, const int* in_sizes, int n_in,
                              void* d_out, int out_size)
{
    const float* query   = (const float*)d_in[0];
    const float* key     = (const float*)d_in[1];
    const float* value   = (const float*)d_in[2];
    const float* wq_w    = (const float*)d_in[3];
    const float* wq_b    = (const float*)d_in[4];
    const float* wk_w    = (const float*)d_in[5];
    const float* wk_b    = (const float*)d_in[6];
    const float* wv_w    = (const float*)d_in[7];
    const float* wv_b    = (const float*)d_in[8];
    const float* dense_w = (const float*)d_in[9];
    const float* dense_b = (const float*)d_in[10];

    float* out = (float*)d_out;
    const long long OUT = (long long)Bc * Sc * HIDc;
    const long long ATT = (long long)Bc * Hc * Sc * Sc;
    const int write_attn = ((long long)out_size >= OUT + ATT) ? 1 : 0;
    float* attn = out + OUT;

    uint32_t *inqh, *inql, *inkh, *inkl, *invh, *invl;
    uint32_t *wqh, *wql, *wkh, *wkl, *wvh, *wvl, *dwh;
    uint32_t *qh, *ql, *ctxh, *ctxl;
    uint4 *khl, *vhl;
    cudaGetSymbolAddress((void**)&inqh, g_inqh);
    cudaGetSymbolAddress((void**)&inql, g_inql);
    cudaGetSymbolAddress((void**)&inkh, g_inkh);
    cudaGetSymbolAddress((void**)&inkl, g_inkl);
    cudaGetSymbolAddress((void**)&invh, g_invh);
    cudaGetSymbolAddress((void**)&invl, g_invl);
    cudaGetSymbolAddress((void**)&wqh, g_wqh);
    cudaGetSymbolAddress((void**)&wql, g_wql);
    cudaGetSymbolAddress((void**)&wkh, g_wkh);
    cudaGetSymbolAddress((void**)&wkl, g_wkl);
    cudaGetSymbolAddress((void**)&wvh, g_wvh);
    cudaGetSymbolAddress((void**)&wvl, g_wvl);
    cudaGetSymbolAddress((void**)&dwh, g_dwh);
    cudaGetSymbolAddress((void**)&qh, g_qh);
    cudaGetSymbolAddress((void**)&ql, g_ql);
    cudaGetSymbolAddress((void**)&khl, g_khl);
    cudaGetSymbolAddress((void**)&vhl, g_vhl);
    cudaGetSymbolAddress((void**)&ctxh, g_ctxh);
    cudaGetSymbolAddress((void**)&ctxl, g_ctxl);

    const int M = Bc * Sc;  // 4096

    // launch #0: all packing
    const int NPK = 3 * NIN + 2 * NWQ + 2 * NWK;
    pack_all<<<(NPK + 255) / 256, 256>>>(query, key, value, wq_w, wk_w, wv_w, dense_w,
                                         inqh, inql, inkh, inkl, invh, invl,
                                         wqh, wql, wkh, wkl, wvh, wvl, dwh);

    // launch #1: merged q/k/v projections (R14 64x64 tiles)
    const float QSCALE = 0.125f * 1.4426950408889634f;
    gemm_qkv<<<dim3(18, 64), 256>>>(inqh, inql, inkh, inkl, invh, invl,
                                    wqh, wql, wq_b, wkh, wkl, wk_b, wvh, wvl, wv_b,
                                    qh, ql, QSCALE, khl, vhl);

    // launch #2: fused attention (R14 version, split-f16 ctx)
    const int smem = 139264 + (512 + 32) * 4;  // 141,440 B
    cudaFuncSetAttribute(attn_kernel, cudaFuncAttributeMaxDynamicSharedMemorySize, smem);
    attn_kernel<<<Bc * Hc * (Sc / QR), 512, smem>>>(qh, ql, khl, vhl,
                                                    attn, ctxh, ctxl, write_attn);

    // launch #3: output projection (f16 2-term)
    gemm_dense<<<dim3(16, 64), 256>>>(ctxh, ctxl, dwh, dense_b, out, M, HIDc, HIDc);
}